// round 13
// baseline (speedup 1.0000x reference)
#include <cuda_runtime.h>
#include <cstdint>

#define BB 64
#define TT 512
#define DD 1024
#define DKK 16
#define NEG_INF (-1e24f)

// scratch (device globals: allocation-free rule)
__device__ float g_q[BB * TT * DKK];
__device__ float g_k[BB * TT * DKK];
__device__ float g_y[(size_t)BB * TT * DD];
__device__ float g_wvT[DD * DD];
__device__ float g_xT[(size_t)BB * DD * TT];   // per-batch x^T, tf32-rounded

// ---------------------------------------------------------------------------
// helpers
// ---------------------------------------------------------------------------
__device__ __forceinline__ uint32_t smem_u32(const void* p) {
    uint32_t a;
    asm("{ .reg .u64 t; cvta.to.shared.u64 t, %1; cvt.u32.u64 %0, t; }"
        : "=r"(a) : "l"(p));
    return a;
}
__device__ __forceinline__ float to_tf32(float x) {
    uint32_t r;
    asm("cvt.rna.tf32.f32 %0, %1;" : "=r"(r) : "f"(x));
    return __uint_as_float(r);
}

#define CP_ASYNC16(dst_u32, src_ptr) \
    asm volatile("cp.async.cg.shared.global [%0], [%1], 16;" \
                 :: "r"(dst_u32), "l"(src_ptr) : "memory")
#define CP_COMMIT() asm volatile("cp.async.commit_group;" ::: "memory")
#define CP_WAIT(n)  asm volatile("cp.async.wait_group %0;" :: "n"(n) : "memory")

__device__ __forceinline__ void mma_tf32(float* d, const uint32_t* a, const uint32_t* b) {
    asm volatile(
        "mma.sync.aligned.m16n8k8.row.col.f32.tf32.tf32.f32 "
        "{%0,%1,%2,%3}, {%4,%5,%6,%7}, {%8,%9}, {%0,%1,%2,%3};"
        : "+f"(d[0]), "+f"(d[1]), "+f"(d[2]), "+f"(d[3])
        : "r"(a[0]), "r"(a[1]), "r"(a[2]), "r"(a[3]), "r"(b[0]), "r"(b[1]));
}

// ldmatrix: 8x8 b16 matrices == 8x4 fp32 tiles; lane -> (row l>>2, f32col l&3)
#define LDSM_X4(r0, r1, r2, r3, addr) \
    asm volatile("ldmatrix.sync.aligned.m8n8.x4.shared.b16 {%0,%1,%2,%3}, [%4];" \
                 : "=r"(r0), "=r"(r1), "=r"(r2), "=r"(r3) : "r"(addr))

// ---------------------------------------------------------------------------
// K1: smem-GEMM qk + fused xT emission + fused WvT transpose (extra CTAs)
// ---------------------------------------------------------------------------
#define QKR 128
#define QKC 64
#define QKPAD 68
#define QK_BLOCKS (BB * TT / QKR)    // 256
#define WVT_BLOCKS 128               // 1024 tiles / 8 warps

__global__ void __launch_bounds__(256, 2)
qk_kernel(const float* __restrict__ x,
          const unsigned char* __restrict__ maskb,
          const float* __restrict__ Wq, const float* __restrict__ bq,
          const float* __restrict__ Wk, const float* __restrict__ bk,
          const float* __restrict__ Wv) {
    __shared__ float xs[QKR * QKPAD];
    __shared__ float ws[QKC * 32];

    const int tid = threadIdx.x;

    // ---- wvt branch: blocks >= QK_BLOCKS transpose Wv -> g_wvT (tf32) ----
    if (blockIdx.x >= QK_BLOCKS) {
        const int wid = tid >> 5, lane = tid & 31;
        const int tileId = (blockIdx.x - QK_BLOCKS) * 8 + wid;   // 0..1023
        const int by = (tileId >> 5) * 32;   // Wv row block
        const int bxc = (tileId & 31) * 32;  // Wv col block
        float* tb = xs + wid * 1056;         // 32x33 buffer per warp
#pragma unroll
        for (int i = 0; i < 32; i++)
            tb[i * 33 + lane] = Wv[(size_t)(by + i) * DD + bxc + lane];
        __syncwarp();
#pragma unroll
        for (int j = 0; j < 32; j++)
            g_wvT[(size_t)(bxc + j) * DD + by + lane] = to_tf32(tb[lane * 33 + j]);
        return;
    }

    const uint32_t xs_u32 = smem_u32(xs);
    const uint32_t ws_u32 = smem_u32(ws);

    const int r0  = blockIdx.x * QKR;
    const int b   = r0 / TT;
    const int sl0 = r0 % TT;

    const int tr = tid >> 3, tc = tid & 7;

    float acc[4][4];
#pragma unroll
    for (int j = 0; j < 4; j++) {
        const int c = tc * 4 + j;
        const float bias = (c < 16) ? bq[c] : bk[c - 16];
#pragma unroll
        for (int i = 0; i < 4; i++) acc[i][j] = bias;
    }

    const int ed   = tid >> 2;
    const int eseg = (tid & 3) * 32;

    for (int ch = 0; ch < 16; ch++) {
        const int k0 = ch * QKC;
        {
            const int kk = tid >> 2, c4 = tid & 3;
            CP_ASYNC16(ws_u32 + (kk * 32 + c4 * 4) * 4,
                       Wq + (size_t)(k0 + kk) * DKK + c4 * 4);
            CP_ASYNC16(ws_u32 + (kk * 32 + 16 + c4 * 4) * 4,
                       Wk + (size_t)(k0 + kk) * DKK + c4 * 4);
        }
#pragma unroll
        for (int it = 0; it < 8; it++) {
            const int idx = tid + it * 256;
            const int row = idx >> 4, c4 = idx & 15;
            CP_ASYNC16(xs_u32 + (row * QKPAD + c4 * 4) * 4,
                       x + (size_t)(r0 + row) * DD + k0 + c4 * 4);
        }
        CP_COMMIT();
        CP_WAIT(0);
        __syncthreads();

#pragma unroll 4
        for (int kk = 0; kk < QKC; kk++) {
            float a[4];
#pragma unroll
            for (int i = 0; i < 4; i++) a[i] = xs[(tr * 4 + i) * QKPAD + kk];
            const float4 w = *reinterpret_cast<const float4*>(&ws[kk * 32 + tc * 4]);
#pragma unroll
            for (int i = 0; i < 4; i++) {
                acc[i][0] += a[i] * w.x;
                acc[i][1] += a[i] * w.y;
                acc[i][2] += a[i] * w.z;
                acc[i][3] += a[i] * w.w;
            }
        }

        {
            float* dst = g_xT + (size_t)b * DD * TT + (size_t)(k0 + ed) * TT + sl0 + eseg;
#pragma unroll
            for (int j = 0; j < 8; j++) {
                float4 v;
                v.x = to_tf32(xs[(eseg + 4 * j + 0) * QKPAD + ed]);
                v.y = to_tf32(xs[(eseg + 4 * j + 1) * QKPAD + ed]);
                v.z = to_tf32(xs[(eseg + 4 * j + 2) * QKPAD + ed]);
                v.w = to_tf32(xs[(eseg + 4 * j + 3) * QKPAD + ed]);
                *reinterpret_cast<float4*>(dst + 4 * j) = v;
            }
        }
        __syncthreads();
    }

    int nz = 0;
#pragma unroll
    for (int p = 0; p < 64; p++)
        if (p & 3) nz |= maskb[p];
    const bool isBool = (nz != 0);

#pragma unroll
    for (int i = 0; i < 4; i++) {
        const int row = r0 + tr * 4 + i;
        const int mv = isBool ? (int)maskb[row]
                              : reinterpret_cast<const int*>(maskb)[row];
#pragma unroll
        for (int j = 0; j < 4; j++) {
            const int c = tc * 4 + j;
            if (c < 16) g_q[row * DKK + c] = acc[i][j];
            else        g_k[row * DKK + (c - 16)] = mv ? NEG_INF : acc[i][j];
        }
    }
}

// ---------------------------------------------------------------------------
// K2: scores + softmax + Y = P@x, causal skip (round 10 form, unchanged)
// ---------------------------------------------------------------------------
#define PST 516
#define KS_STRIDE 17
#define BKP2 36
#define BBUF_FLOATS (128 * BKP2)                      // 4608
#define REGION_FLOATS (3 * BBUF_FLOATS)               // 13824
#define ATT_SMEM_FLOATS (64 * PST + REGION_FLOATS)    // 46848

__global__ void __launch_bounds__(256, 1)
attn_kernel() {
    extern __shared__ float sm[];
    __shared__ int s_flag;
    float* Ps = sm;
    float* rg = sm + 64 * PST;
    float* ks = rg;
    float* qs = rg + 512 * KS_STRIDE;
    const uint32_t ps_u32 = smem_u32(sm);
    const uint32_t rg_u32 = smem_u32(rg);

    const int b    = blockIdx.y;
    const int tile = blockIdx.x;
    const int tid  = threadIdx.x;
    const int qbase = b * TT + tile * 64;

    if (tid == 0) s_flag = 0;
    for (int i = tid; i < TT * DKK; i += 256) {
        int s = i >> 4, d = i & 15;
        ks[s * KS_STRIDE + d] = g_k[(b * TT + s) * DKK + d];
    }
    for (int i = tid; i < 64 * DKK; i += 256)
        qs[i] = g_q[qbase * DKK + i];
    __syncthreads();

    // ---- scores (only s < 64*(tile+1) computed; tail set to NEG_INF) ----
    {
        const int r  = tid >> 2;
        const int tq = tile * 64 + r;
        float qreg[16];
#pragma unroll
        for (int d = 0; d < 16; d++) qreg[d] = qs[r * 16 + d];
        const int s0 = tid & 3;
        const int jmax = 16 * (tile + 1);
        for (int j = 0; j < jmax; j++) {
            int s = s0 + 4 * j;
            float dot = 0.f;
#pragma unroll
            for (int d = 0; d < 16; d++) dot += qreg[d] * ks[s * KS_STRIDE + d];
            Ps[r * PST + s] = (s > tq) ? NEG_INF : dot * 4.0f;
        }
        for (int j = jmax; j < 128; j++)
            Ps[r * PST + s0 + 4 * j] = NEG_INF;
    }
    __syncthreads();

    // ---- softmax (write P as tf32); detect pathological rows ----
    {
        const int w = tid >> 5, l = tid & 31;
        for (int rr = 0; rr < 8; rr++) {
            const int r = w * 8 + rr;
            float v[16];
            float m = -3.4e38f;
#pragma unroll
            for (int i = 0; i < 16; i++) {
                v[i] = Ps[r * PST + l + 32 * i];
                m = fmaxf(m, v[i]);
            }
#pragma unroll
            for (int off = 16; off > 0; off >>= 1)
                m = fmaxf(m, __shfl_xor_sync(0xffffffffu, m, off));
            if (l == 0 && m < -1e20f) s_flag = 1;
            float ssum = 0.f;
#pragma unroll
            for (int i = 0; i < 16; i++) { v[i] = __expf(v[i] - m); ssum += v[i]; }
#pragma unroll
            for (int off = 16; off > 0; off >>= 1)
                ssum += __shfl_xor_sync(0xffffffffu, ssum, off);
            const float inv = 1.0f / ssum;
#pragma unroll
            for (int i = 0; i < 16; i++)
                Ps[r * PST + l + 32 * i] = to_tf32(v[i] * inv);
        }
    }
    __syncthreads();

    // ---- Y = P @ x via mma + ldmatrix, 3-stage, causal chunk skip ----
    const int wid = tid >> 5, lane = tid & 31;
    const int wm = (wid >> 2) * 32;
    const int wn = (wid & 3) * 32;
    const int lm = lane >> 2, lk = lane & 3;
    const int srow = tid >> 1;
    const int sc4  = (tid & 1) * 4;

    const int lr  = lane & 7;
    const int ah  = (lane >> 3) & 1;
    const int ac  = lane >> 4;
    const uint32_t aAddr0 = ps_u32 + ((wm + ah * 8 + lr) * PST + ac * 4) * 4;
    const uint32_t bAddrX4 = rg_u32 +
        ((wn + ((lane >> 4) & 1) * 8 + lr) * BKP2 + ((lane >> 3) & 1) * 4) * 4;

    const float* xTb = g_xT + (size_t)b * DD * TT;

    const int nch = s_flag ? 16 : 2 * (tile + 1);   // k-chunks per nb
    const int tot = 8 * nch;

#define PREF2(NB, KC, BUF) do {                                                      \
        uint32_t dstb = rg_u32 + ((BUF) * BBUF_FLOATS + srow * BKP2 + sc4 * 4) * 4;  \
        const float* src = xTb + (size_t)((NB) * 128 + srow) * TT + (KC) * 32 + sc4 * 4; \
        _Pragma("unroll")                                                            \
        for (int q = 0; q < 4; q++) CP_ASYNC16(dstb + q * 16, src + q * 4);          \
    } while (0)

    float acc[2][4][4];
#pragma unroll
    for (int i = 0; i < 2; i++)
#pragma unroll
        for (int j = 0; j < 4; j++)
#pragma unroll
            for (int r = 0; r < 4; r++) acc[i][j][r] = 0.f;

    int nbP = 0, kcP = 0;
    PREF2(nbP, kcP, 0); CP_COMMIT();
    if (++kcP == nch) { kcP = 0; nbP++; }
    PREF2(nbP, kcP, 1); CP_COMMIT();
    if (++kcP == nch) { kcP = 0; nbP++; }

    int nbC = 0, kcC = 0;
    for (int st = 0; st < tot; st++) {
        const int buf = st % 3;
        if (st + 2 < tot) { CP_WAIT(1); } else { CP_WAIT(0); }
        __syncthreads();
        if (st + 2 < tot) {
            PREF2(nbP, kcP, (st + 2) % 3); CP_COMMIT();
            if (++kcP == nch) { kcP = 0; nbP++; }
        }

        const uint32_t bBuf = bAddrX4 + buf * BBUF_FLOATS * 4;
        const int kbase = kcC * 32;
#pragma unroll
        for (int ksu = 0; ksu < 4; ksu++) {
            const int kb = kbase + ksu * 8;
            uint32_t a[2][4], bfr[4][2];
#pragma unroll
            for (int mt = 0; mt < 2; mt++)
                LDSM_X4(a[mt][0], a[mt][1], a[mt][2], a[mt][3],
                        aAddr0 + (mt * 16 * PST + kb) * 4);
#pragma unroll
            for (int p = 0; p < 2; p++)
                LDSM_X4(bfr[2 * p][0], bfr[2 * p][1], bfr[2 * p + 1][0], bfr[2 * p + 1][1],
                        bBuf + (p * 16 * BKP2 + ksu * 8) * 4);
#pragma unroll
            for (int mt = 0; mt < 2; mt++)
#pragma unroll
                for (int nt = 0; nt < 4; nt++)
                    mma_tf32(acc[mt][nt], a[mt], bfr[nt]);
        }

        if (kcC == nch - 1) {
            const int nb = nbC * 128;
#pragma unroll
            for (int mt = 0; mt < 2; mt++) {
                const int row = qbase + wm + mt * 16 + lm;
#pragma unroll
                for (int nt = 0; nt < 4; nt++) {
                    const int col = nb + wn + nt * 8 + 2 * lk;
                    float2 v0 = { to_tf32(acc[mt][nt][0]), to_tf32(acc[mt][nt][1]) };
                    float2 v1 = { to_tf32(acc[mt][nt][2]), to_tf32(acc[mt][nt][3]) };
                    *reinterpret_cast<float2*>(g_y + (size_t)row * DD + col) = v0;
                    *reinterpret_cast<float2*>(g_y + (size_t)(row + 8) * DD + col) = v1;
#pragma unroll
                    for (int r = 0; r < 4; r++) acc[mt][nt][r] = 0.f;
                }
            }
        }
        if (++kcC == nch) { kcC = 0; nbC++; }
    }
#undef PREF2
}

// ---------------------------------------------------------------------------
// K3: out = Y @ WvT^T + bv  — BM=64, warp tile 32x32, 2-stage, 3 CTAs/SM
// acc = 32 regs/thread -> no spills at the 80-reg/3-CTA budget
// ---------------------------------------------------------------------------
#define BM3 64
#define BN3 128
#define BK3 32
#define BKP3 36
#define A3_FLOATS (BM3 * BKP3)              // 2304
#define B3_FLOATS (BN3 * BKP3)              // 4608
#define G3_STAGE (A3_FLOATS + B3_FLOATS)    // 6912
#define NSTAGE3 (DD / BK3)                  // 32

__global__ void __launch_bounds__(256, 3)
gemm3_mma(const float* __restrict__ bv, float* __restrict__ out) {
    extern __shared__ float sm[];
    const uint32_t sb = smem_u32(sm);

    const int tid  = threadIdx.x;
    const int wid  = tid >> 5, lane = tid & 31;
    const int wm   = (wid >> 2) * 32;     // 0 or 32
    const int wn   = (wid & 3) * 32;      // 0..96
    const int lm   = lane >> 2, lk = lane & 3;
    const int n0   = blockIdx.x * BN3;
    const int m0   = blockIdx.y * BM3;

    const float* Arow = g_y   + (size_t)m0 * DD;
    const float* Brow = g_wvT + (size_t)n0 * DD;

    const int srow = tid >> 3;            // 0..31 (8 float4 per row)
    const int sc4  = (tid & 7);           // float4 index 0..7

    const int lr = lane & 7;
    const int ah = (lane >> 3) & 1;
    const int ac = lane >> 4;
    const uint32_t aAddr0 = sb + ((wm + ah * 8 + lr) * BKP3 + ac * 4) * 4;
    const uint32_t bAddrX4 = sb + A3_FLOATS * 4 +
        ((wn + ((lane >> 4) & 1) * 8 + lr) * BKP3 + ((lane >> 3) & 1) * 4) * 4;

#define PREFETCH3(S, ST) do {                                                          \
        const int k0 = (S) * BK3;                                                      \
        /* A: 512 float4 = 2 passes; row = idx>>3, c4 = idx&7 */                       \
        _Pragma("unroll")                                                              \
        for (int t = 0; t < 2; t++) {                                                  \
            const int idx = tid + t * 256;                                             \
            const int row = idx >> 3, c4 = idx & 7;                                    \
            CP_ASYNC16(sb + ((ST) * G3_STAGE + row * BKP3 + c4 * 4) * 4,               \
                       Arow + (size_t)row * DD + k0 + c4 * 4);                         \
        }                                                                              \
        /* B: 1024 float4 = 4 passes */                                                \
        _Pragma("unroll")                                                              \
        for (int t = 0; t < 4; t++) {                                                  \
            const int idx = tid + t * 256;                                             \
            const int row = idx >> 3, c4 = idx & 7;                                    \
            CP_ASYNC16(sb + ((ST) * G3_STAGE + A3_FLOATS + row * BKP3 + c4 * 4) * 4,   \
                       Brow + (size_t)row * DD + k0 + c4 * 4);                         \
        }                                                                              \
    } while (0)

    float acc[2][4][4];
#pragma unroll
    for (int i = 0; i < 2; i++)
#pragma unroll
        for (int j = 0; j < 4; j++)
#pragma unroll
            for (int r = 0; r < 4; r++) acc[i][j][r] = 0.f;

    PREFETCH3(0, 0); CP_COMMIT();

    for (int s = 0; s < NSTAGE3; s++) {
        const int st = s & 1;
        if (s + 1 < NSTAGE3) {
            PREFETCH3(s + 1, st ^ 1); CP_COMMIT();
            CP_WAIT(1);
        } else {
            CP_WAIT(0);
        }
        __syncthreads();

        const uint32_t aBuf = aAddr0 + st * G3_STAGE * 4;
        const uint32_t bBuf = bAddrX4 + st * G3_STAGE * 4;
#pragma unroll
        for (int ksu = 0; ksu < 4; ksu++) {
            uint32_t a[2][4], b[4][2];
#pragma unroll
            for (int mt = 0; mt < 2; mt++)
                LDSM_X4(a[mt][0], a[mt][1], a[mt][2], a[mt][3],
                        aBuf + (mt * 16 * BKP3 + ksu * 8) * 4);
#pragma unroll
            for (int p = 0; p < 2; p++)
                LDSM_X4(b[2 * p][0], b[2 * p][1], b[2 * p + 1][0], b[2 * p + 1][1],
                        bBuf + (p * 16 * BKP3 + ksu * 8) * 4);
#pragma unroll
            for (int mt = 0; mt < 2; mt++)
#pragma unroll
                for (int nt = 0; nt < 4; nt++)
                    mma_tf32(acc[mt][nt], a[mt], b[nt]);
        }
        __syncthreads();
    }
#undef PREFETCH3

#pragma unroll
    for (int mt = 0; mt < 2; mt++) {
        const int row = m0 + wm + mt * 16 + lm;
#pragma unroll
        for (int nt = 0; nt < 4; nt++) {
            const int col = n0 + wn + nt * 8 + 2 * lk;
            const float b0 = bv[col], b1 = bv[col + 1];
            float2 v0 = { acc[mt][nt][0] + b0, acc[mt][nt][1] + b1 };
            float2 v1 = { acc[mt][nt][2] + b0, acc[mt][nt][3] + b1 };
            *reinterpret_cast<float2*>(out + (size_t)row * DD + col) = v0;
            *reinterpret_cast<float2*>(out + (size_t)(row + 8) * DD + col) = v1;
        }
    }
}

// ---------------------------------------------------------------------------
extern "C" void kernel_launch(void* const* d_in, const int* in_sizes, int n_in,
                              void* d_out, int out_size) {
    const float*         x    = (const float*)d_in[0];
    const unsigned char* mask = (const unsigned char*)d_in[1];
    const float*         Wq   = (const float*)d_in[2];
    const float*         bq   = (const float*)d_in[3];
    const float*         Wk   = (const float*)d_in[4];
    const float*         bk   = (const float*)d_in[5];
    const float*         Wv   = (const float*)d_in[6];
    const float*         bv   = (const float*)d_in[7];
    float* out = (float*)d_out;

    qk_kernel<<<QK_BLOCKS + WVT_BLOCKS, 256>>>(x, mask, Wq, bq, Wk, bk, Wv);

    const size_t asmem = ATT_SMEM_FLOATS * sizeof(float);
    cudaFuncSetAttribute(attn_kernel, cudaFuncAttributeMaxDynamicSharedMemorySize, (int)asmem);
    attn_kernel<<<dim3(TT / 64, BB), 256, asmem>>>();

    const size_t gsmem = 2 * G3_STAGE * sizeof(float);   // 55296 B
    cudaFuncSetAttribute(gemm3_mma, cudaFuncAttributeMaxDynamicSharedMemorySize, (int)gsmem);
    gemm3_mma<<<dim3(DD / BN3, BB * TT / BM3), 256, gsmem>>>(bv, out);
}

// round 14
// speedup vs baseline: 2.6206x; 2.6206x over previous
#include <cuda_runtime.h>
#include <cuda_fp16.h>
#include <cstdint>

#define BB 64
#define TT 512
#define DD 1024
#define DKK 16
#define NEG_INF (-1e24f)

// scratch (device globals: allocation-free rule)
__device__ float  g_q[BB * TT * DKK];
__device__ float  g_k[BB * TT * DKK];
__device__ __half g_yh[(size_t)BB * TT * DD];
__device__ __half g_wvTh[DD * DD];
__device__ __half g_xTh[(size_t)BB * DD * TT];

// ---------------------------------------------------------------------------
// helpers
// ---------------------------------------------------------------------------
__device__ __forceinline__ uint32_t smem_u32(const void* p) {
    uint32_t a;
    asm("{ .reg .u64 t; cvta.to.shared.u64 t, %1; cvt.u32.u64 %0, t; }"
        : "=r"(a) : "l"(p));
    return a;
}
__device__ __forceinline__ uint32_t f2h2(float a, float b) {
    __half2 h = __floats2half2_rn(a, b);
    return *reinterpret_cast<uint32_t*>(&h);
}

#define CP_ASYNC16(dst_u32, src_ptr) \
    asm volatile("cp.async.cg.shared.global [%0], [%1], 16;" \
                 :: "r"(dst_u32), "l"(src_ptr) : "memory")
#define CP_COMMIT() asm volatile("cp.async.commit_group;" ::: "memory")
#define CP_WAIT(n)  asm volatile("cp.async.wait_group %0;" :: "n"(n) : "memory")

__device__ __forceinline__ void mma_f16(float* d, const uint32_t* a, const uint32_t* b) {
    asm volatile(
        "mma.sync.aligned.m16n8k16.row.col.f32.f16.f16.f32 "
        "{%0,%1,%2,%3}, {%4,%5,%6,%7}, {%8,%9}, {%0,%1,%2,%3};"
        : "+f"(d[0]), "+f"(d[1]), "+f"(d[2]), "+f"(d[3])
        : "r"(a[0]), "r"(a[1]), "r"(a[2]), "r"(a[3]), "r"(b[0]), "r"(b[1]));
}

#define LDSM_X4(r0, r1, r2, r3, addr) \
    asm volatile("ldmatrix.sync.aligned.m8n8.x4.shared.b16 {%0,%1,%2,%3}, [%4];" \
                 : "=r"(r0), "=r"(r1), "=r"(r2), "=r"(r3) : "r"(addr))

// ---------------------------------------------------------------------------
// K0: WvT[n][k] = half(Wv[k][n])
// ---------------------------------------------------------------------------
__global__ void wvt_kernel(const float* __restrict__ Wv) {
    __shared__ float t[32][33];
    const int bx = blockIdx.x * 32, by = blockIdx.y * 32;
    const int tx = threadIdx.x, ty = threadIdx.y;
#pragma unroll
    for (int i = 0; i < 32; i += 8)
        t[ty + i][tx] = Wv[(size_t)(by + ty + i) * DD + bx + tx];
    __syncthreads();
#pragma unroll
    for (int i = 0; i < 32; i += 8)
        g_wvTh[(size_t)(bx + ty + i) * DD + by + tx] = __float2half(t[tx][ty + i]);
}

// ---------------------------------------------------------------------------
// K1: smem-GEMM qk + fused xT (half) emission  (R10 structure)
// ---------------------------------------------------------------------------
#define QKR 128
#define QKC 64
#define QKPAD 68

__global__ void __launch_bounds__(256, 2)
qk_kernel(const float* __restrict__ x,
          const unsigned char* __restrict__ maskb,
          const float* __restrict__ Wq, const float* __restrict__ bq,
          const float* __restrict__ Wk, const float* __restrict__ bk) {
    __shared__ float xs[QKR * QKPAD];
    __shared__ float ws[QKC * 32];
    const uint32_t xs_u32 = smem_u32(xs);
    const uint32_t ws_u32 = smem_u32(ws);

    const int tid = threadIdx.x;
    const int r0  = blockIdx.x * QKR;
    const int b   = r0 / TT;
    const int sl0 = r0 % TT;

    const int tr = tid >> 3, tc = tid & 7;

    float acc[4][4];
#pragma unroll
    for (int j = 0; j < 4; j++) {
        const int c = tc * 4 + j;
        const float bias = (c < 16) ? bq[c] : bk[c - 16];
#pragma unroll
        for (int i = 0; i < 4; i++) acc[i][j] = bias;
    }

    const int ed   = tid >> 2;
    const int eseg = (tid & 3) * 32;

    for (int ch = 0; ch < 16; ch++) {
        const int k0 = ch * QKC;
        {
            const int kk = tid >> 2, c4 = tid & 3;
            CP_ASYNC16(ws_u32 + (kk * 32 + c4 * 4) * 4,
                       Wq + (size_t)(k0 + kk) * DKK + c4 * 4);
            CP_ASYNC16(ws_u32 + (kk * 32 + 16 + c4 * 4) * 4,
                       Wk + (size_t)(k0 + kk) * DKK + c4 * 4);
        }
#pragma unroll
        for (int it = 0; it < 8; it++) {
            const int idx = tid + it * 256;
            const int row = idx >> 4, c4 = idx & 15;
            CP_ASYNC16(xs_u32 + (row * QKPAD + c4 * 4) * 4,
                       x + (size_t)(r0 + row) * DD + k0 + c4 * 4);
        }
        CP_COMMIT();
        CP_WAIT(0);
        __syncthreads();

#pragma unroll 4
        for (int kk = 0; kk < QKC; kk++) {
            float a[4];
#pragma unroll
            for (int i = 0; i < 4; i++) a[i] = xs[(tr * 4 + i) * QKPAD + kk];
            const float4 w = *reinterpret_cast<const float4*>(&ws[kk * 32 + tc * 4]);
#pragma unroll
            for (int i = 0; i < 4; i++) {
                acc[i][0] += a[i] * w.x;
                acc[i][1] += a[i] * w.y;
                acc[i][2] += a[i] * w.z;
                acc[i][3] += a[i] * w.w;
            }
        }

        // emit xT half for dims k0..k0+63, s = sl0..sl0+127
        {
            __half* dst = g_xTh + (size_t)b * DD * TT + (size_t)(k0 + ed) * TT + sl0 + eseg;
#pragma unroll
            for (int j = 0; j < 4; j++) {
                uint4 v;
                v.x = f2h2(xs[(eseg + 8 * j + 0) * QKPAD + ed], xs[(eseg + 8 * j + 1) * QKPAD + ed]);
                v.y = f2h2(xs[(eseg + 8 * j + 2) * QKPAD + ed], xs[(eseg + 8 * j + 3) * QKPAD + ed]);
                v.z = f2h2(xs[(eseg + 8 * j + 4) * QKPAD + ed], xs[(eseg + 8 * j + 5) * QKPAD + ed]);
                v.w = f2h2(xs[(eseg + 8 * j + 6) * QKPAD + ed], xs[(eseg + 8 * j + 7) * QKPAD + ed]);
                *reinterpret_cast<uint4*>(dst + 8 * j) = v;
            }
        }
        __syncthreads();
    }

    int nz = 0;
#pragma unroll
    for (int p = 0; p < 64; p++)
        if (p & 3) nz |= maskb[p];
    const bool isBool = (nz != 0);

#pragma unroll
    for (int i = 0; i < 4; i++) {
        const int row = r0 + tr * 4 + i;
        const int mv = isBool ? (int)maskb[row]
                              : reinterpret_cast<const int*>(maskb)[row];
#pragma unroll
        for (int j = 0; j < 4; j++) {
            const int c = tc * 4 + j;
            if (c < 16) g_q[row * DKK + c] = acc[i][j];
            else        g_k[row * DKK + (c - 16)] = mv ? NEG_INF : acc[i][j];
        }
    }
}

// ---------------------------------------------------------------------------
// K2: scores(fp32) + softmax -> P half; Y = P@x via fp16 mma, causal skip
// smem bytes: Ps f32 64x513 | region{ ks/qs -> Psh half 64x520 | B ring 3x10240 }
// ---------------------------------------------------------------------------
#define PST 513
#define PSTH 520
#define PS_BYTES (64 * PST * 4)              // 131328
#define PSH_BYTES (64 * PSTH * 2)            // 66560
#define BKP2H 40
#define BBUF_B (128 * BKP2H * 2)             // 10240
#define ATT_SMEM_BYTES (PS_BYTES + PSH_BYTES + 3 * BBUF_B)   // 228608

__global__ void __launch_bounds__(256, 1)
attn_kernel() {
    extern __shared__ char smc[];
    __shared__ int s_flag;
    float* Ps = reinterpret_cast<float*>(smc);
    char*  region = smc + PS_BYTES;
    float* ks = reinterpret_cast<float*>(region);
    float* qs = ks + 512 * 17;
    __half* Psh = reinterpret_cast<__half*>(region);
    const uint32_t psh_u32 = smem_u32(region);
    const uint32_t bring_u32 = psh_u32 + PSH_BYTES;

    const int b    = blockIdx.y;
    const int tile = blockIdx.x;
    const int tid  = threadIdx.x;
    const int qbase = b * TT + tile * 64;

    if (tid == 0) s_flag = 0;
    for (int i = tid; i < TT * DKK; i += 256) {
        int s = i >> 4, d = i & 15;
        ks[s * 17 + d] = g_k[(b * TT + s) * DKK + d];
    }
    for (int i = tid; i < 64 * DKK; i += 256)
        qs[i] = g_q[qbase * DKK + i];
    __syncthreads();

    // ---- scores (only s < 64*(tile+1); tail NEG_INF) ----
    {
        const int r  = tid >> 2;
        const int tq = tile * 64 + r;
        float qreg[16];
#pragma unroll
        for (int d = 0; d < 16; d++) qreg[d] = qs[r * 16 + d];
        const int s0 = tid & 3;
        const int jmax = 16 * (tile + 1);
        for (int j = 0; j < jmax; j++) {
            int s = s0 + 4 * j;
            float dot = 0.f;
#pragma unroll
            for (int d = 0; d < 16; d++) dot += qreg[d] * ks[s * 17 + d];
            Ps[r * PST + s] = (s > tq) ? NEG_INF : dot * 4.0f;
        }
        for (int j = jmax; j < 128; j++)
            Ps[r * PST + s0 + 4 * j] = NEG_INF;
    }
    __syncthreads();

    // ---- softmax; write P as half into Psh (overwrites dead ks/qs) ----
    {
        const int w = tid >> 5, l = tid & 31;
        for (int rr = 0; rr < 8; rr++) {
            const int r = w * 8 + rr;
            float v[16];
            float m = -3.4e38f;
#pragma unroll
            for (int i = 0; i < 16; i++) {
                v[i] = Ps[r * PST + l + 32 * i];
                m = fmaxf(m, v[i]);
            }
#pragma unroll
            for (int off = 16; off > 0; off >>= 1)
                m = fmaxf(m, __shfl_xor_sync(0xffffffffu, m, off));
            if (l == 0 && m < -1e20f) s_flag = 1;
            float ssum = 0.f;
#pragma unroll
            for (int i = 0; i < 16; i++) { v[i] = __expf(v[i] - m); ssum += v[i]; }
#pragma unroll
            for (int off = 16; off > 0; off >>= 1)
                ssum += __shfl_xor_sync(0xffffffffu, ssum, off);
            const float inv = 1.0f / ssum;
#pragma unroll
            for (int i = 0; i < 16; i++)
                Psh[r * PSTH + l + 32 * i] = __float2half(v[i] * inv);
        }
    }
    __syncthreads();

    // ---- Y = P @ x via fp16 mma + ldmatrix, 3-stage ring, causal skip ----
    const int wid = tid >> 5, lane = tid & 31;
    const int wm = (wid >> 2) * 32;
    const int wn = (wid & 3) * 32;
    const int lm = lane >> 2, lk = lane & 3;
    const int srow = tid >> 2;                  // 0..63? no: B stage = 512 chunks
    const int lr  = lane & 7;
    const int ah  = (lane >> 3) & 1;
    const int ac  = lane >> 4;

    const uint32_t aAddr0 = psh_u32 + ((wm + ah * 8 + lr) * PSTH + ac * 8) * 2;
    const uint32_t bAddrX4 = bring_u32 +
        ((wn + ((lane >> 4) & 1) * 8 + lr) * BKP2H + ((lane >> 3) & 1) * 8) * 2;

    const __half* xTb = g_xTh + (size_t)b * DD * TT;

    const int nch = s_flag ? 16 : 2 * (tile + 1);   // 32-half k-chunks per nb
    const int tot = 8 * nch;

    // stage: 128 rows x 32 halves = 512 x 16B chunks; 2 per thread
#define PREF2(NB, KC, BUF) do {                                                      \
        _Pragma("unroll")                                                            \
        for (int t = 0; t < 2; t++) {                                                \
            const int idx = tid + t * 256;                                           \
            const int row = idx >> 2, c8 = idx & 3;                                  \
            CP_ASYNC16(bring_u32 + (BUF) * BBUF_B + (row * BKP2H + c8 * 8) * 2,      \
                       xTb + (size_t)((NB) * 128 + row) * TT + (KC) * 32 + c8 * 8);  \
        }                                                                            \
    } while (0)

    float acc[2][4][4];
#pragma unroll
    for (int i = 0; i < 2; i++)
#pragma unroll
        for (int j = 0; j < 4; j++)
#pragma unroll
            for (int r = 0; r < 4; r++) acc[i][j][r] = 0.f;

    int nbP = 0, kcP = 0;
    PREF2(nbP, kcP, 0); CP_COMMIT();
    if (++kcP == nch) { kcP = 0; nbP++; }
    PREF2(nbP, kcP, 1); CP_COMMIT();
    if (++kcP == nch) { kcP = 0; nbP++; }

    int nbC = 0, kcC = 0;
    for (int st = 0; st < tot; st++) {
        const int buf = st % 3;
        if (st + 2 < tot) { CP_WAIT(1); } else { CP_WAIT(0); }
        __syncthreads();
        if (st + 2 < tot) {
            PREF2(nbP, kcP, (st + 2) % 3); CP_COMMIT();
            if (++kcP == nch) { kcP = 0; nbP++; }
        }

        const uint32_t bBuf = bAddrX4 + buf * BBUF_B;
        const int kbase = kcC * 32;
#pragma unroll
        for (int ksu = 0; ksu < 2; ksu++) {
            const int kp = kbase + ksu * 16;
            uint32_t a[2][4], bfr[4][2];
#pragma unroll
            for (int mt = 0; mt < 2; mt++)
                LDSM_X4(a[mt][0], a[mt][1], a[mt][2], a[mt][3],
                        aAddr0 + (mt * 16 * PSTH + kp) * 2);
#pragma unroll
            for (int p = 0; p < 2; p++)
                LDSM_X4(bfr[2 * p][0], bfr[2 * p][1], bfr[2 * p + 1][0], bfr[2 * p + 1][1],
                        bBuf + (p * 16 * BKP2H + ksu * 16) * 2);
#pragma unroll
            for (int mt = 0; mt < 2; mt++)
#pragma unroll
                for (int nt = 0; nt < 4; nt++)
                    mma_f16(acc[mt][nt], a[mt], bfr[nt]);
        }

        if (kcC == nch - 1) {
            const int nb = nbC * 128;
#pragma unroll
            for (int mt = 0; mt < 2; mt++) {
                const int row = qbase + wm + mt * 16 + lm;
#pragma unroll
                for (int nt = 0; nt < 4; nt++) {
                    const int col = nb + wn + nt * 8 + 2 * lk;
                    *reinterpret_cast<uint32_t*>(g_yh + (size_t)row * DD + col) =
                        f2h2(acc[mt][nt][0], acc[mt][nt][1]);
                    *reinterpret_cast<uint32_t*>(g_yh + (size_t)(row + 8) * DD + col) =
                        f2h2(acc[mt][nt][2], acc[mt][nt][3]);
#pragma unroll
                    for (int r = 0; r < 4; r++) acc[mt][nt][r] = 0.f;
                }
            }
        }
        if (++kcC == nch) { kcC = 0; nbC++; }
    }
#undef PREF2
}

// ---------------------------------------------------------------------------
// K3: out = Y @ WvT^T + bv — fp16 mma, BM=128 BN=128 BK=64h, 2-stage, 2 CTA/SM
// ---------------------------------------------------------------------------
#define BK3H 64
#define BKP3H 72
#define A3_B (128 * BKP3H * 2)          // 18432
#define G3S (2 * A3_B)                  // 36864 per stage (A+B)
#define NST3 (DD / BK3H)                // 16

__global__ void __launch_bounds__(256, 2)
gemm3_mma(const float* __restrict__ bv, float* __restrict__ out) {
    extern __shared__ char smc[];
    const uint32_t sb = smem_u32(smc);

    const int tid  = threadIdx.x;
    const int wid  = tid >> 5, lane = tid & 31;
    const int wm   = (wid >> 2) * 64;
    const int wn   = (wid & 3) * 32;
    const int lm   = lane >> 2, lk = lane & 3;
    const int n0   = blockIdx.x * 128;
    const int m0   = blockIdx.y * 128;

    const __half* Arow = g_yh   + (size_t)m0 * DD;
    const __half* Brow = g_wvTh + (size_t)n0 * DD;

    const int lr = lane & 7;
    const int ah = (lane >> 3) & 1;
    const int ac = lane >> 4;
    const uint32_t aAddr0 = sb + ((wm + ah * 8 + lr) * BKP3H + ac * 8) * 2;
    const uint32_t bAddrX4 = sb + A3_B +
        ((wn + ((lane >> 4) & 1) * 8 + lr) * BKP3H + ((lane >> 3) & 1) * 8) * 2;

    // stage: A 128x64h = 1024 chunks (4/thread), B same
#define PREFETCH(S, ST) do {                                                          \
        const int k0 = (S) * BK3H;                                                    \
        _Pragma("unroll")                                                             \
        for (int t = 0; t < 4; t++) {                                                 \
            const int idx = tid + t * 256;                                            \
            const int row = idx >> 3, c8 = idx & 7;                                   \
            CP_ASYNC16(sb + (ST) * G3S + (row * BKP3H + c8 * 8) * 2,                  \
                       Arow + (size_t)row * DD + k0 + c8 * 8);                        \
            CP_ASYNC16(sb + (ST) * G3S + A3_B + (row * BKP3H + c8 * 8) * 2,           \
                       Brow + (size_t)row * DD + k0 + c8 * 8);                        \
        }                                                                             \
    } while (0)

    float acc[4][4][4];
#pragma unroll
    for (int i = 0; i < 4; i++)
#pragma unroll
        for (int j = 0; j < 4; j++)
#pragma unroll
            for (int r = 0; r < 4; r++) acc[i][j][r] = 0.f;

    PREFETCH(0, 0); CP_COMMIT();

    for (int s = 0; s < NST3; s++) {
        const int st = s & 1;
        if (s + 1 < NST3) {
            PREFETCH(s + 1, st ^ 1); CP_COMMIT();
            CP_WAIT(1);
        } else {
            CP_WAIT(0);
        }
        __syncthreads();

        const uint32_t aBuf = aAddr0 + st * G3S;
        const uint32_t bBuf = bAddrX4 + st * G3S;
#pragma unroll
        for (int ksu = 0; ksu < 4; ksu++) {
            uint32_t a[4][4], b[4][2];
#pragma unroll
            for (int mt = 0; mt < 4; mt++)
                LDSM_X4(a[mt][0], a[mt][1], a[mt][2], a[mt][3],
                        aBuf + (mt * 16 * BKP3H + ksu * 16) * 2);
#pragma unroll
            for (int p = 0; p < 2; p++)
                LDSM_X4(b[2 * p][0], b[2 * p][1], b[2 * p + 1][0], b[2 * p + 1][1],
                        bBuf + (p * 16 * BKP3H + ksu * 16) * 2);
#pragma unroll
            for (int mt = 0; mt < 4; mt++)
#pragma unroll
                for (int nt = 0; nt < 4; nt++)
                    mma_f16(acc[mt][nt], a[mt], b[nt]);
        }
        __syncthreads();
    }
#undef PREFETCH

#pragma unroll
    for (int mt = 0; mt < 4; mt++) {
        const int row = m0 + wm + mt * 16 + lm;
#pragma unroll
        for (int nt = 0; nt < 4; nt++) {
            const int col = n0 + wn + nt * 8 + 2 * lk;
            const float b0 = bv[col], b1 = bv[col + 1];
            float2 v0 = { acc[mt][nt][0] + b0, acc[mt][nt][1] + b1 };
            float2 v1 = { acc[mt][nt][2] + b0, acc[mt][nt][3] + b1 };
            *reinterpret_cast<float2*>(out + (size_t)row * DD + col) = v0;
            *reinterpret_cast<float2*>(out + (size_t)(row + 8) * DD + col) = v1;
        }
    }
}

// ---------------------------------------------------------------------------
extern "C" void kernel_launch(void* const* d_in, const int* in_sizes, int n_in,
                              void* d_out, int out_size) {
    const float*         x    = (const float*)d_in[0];
    const unsigned char* mask = (const unsigned char*)d_in[1];
    const float*         Wq   = (const float*)d_in[2];
    const float*         bq   = (const float*)d_in[3];
    const float*         Wk   = (const float*)d_in[4];
    const float*         bk   = (const float*)d_in[5];
    const float*         Wv   = (const float*)d_in[6];
    const float*         bv   = (const float*)d_in[7];
    float* out = (float*)d_out;

    wvt_kernel<<<dim3(32, 32), dim3(32, 8)>>>(Wv);
    qk_kernel<<<BB * TT / QKR, 256>>>(x, mask, Wq, bq, Wk, bk);

    cudaFuncSetAttribute(attn_kernel, cudaFuncAttributeMaxDynamicSharedMemorySize,
                         ATT_SMEM_BYTES);
    attn_kernel<<<dim3(TT / 64, BB), 256, ATT_SMEM_BYTES>>>();

    const size_t gsmem = 2 * G3S;   // 73728 B
    cudaFuncSetAttribute(gemm3_mma, cudaFuncAttributeMaxDynamicSharedMemorySize, (int)gsmem);
    gemm3_mma<<<dim3(DD / 128, BB * TT / 128), 256, gsmem>>>(bv, out);
}

// round 15
// speedup vs baseline: 2.8355x; 1.0820x over previous
#include <cuda_runtime.h>
#include <cuda_fp16.h>
#include <cstdint>

#define BB 64
#define TT 512
#define DD 1024
#define DKK 16
#define NEG_INF (-1e24f)

// scratch (device globals: allocation-free rule)
__device__ float  g_q[BB * TT * DKK];
__device__ float  g_k[BB * TT * DKK];
__device__ __half g_yh[(size_t)BB * TT * DD];
__device__ __half g_wvTh[DD * DD];
__device__ __half g_xTh[(size_t)BB * DD * TT];

// ---------------------------------------------------------------------------
// helpers
// ---------------------------------------------------------------------------
__device__ __forceinline__ uint32_t smem_u32(const void* p) {
    uint32_t a;
    asm("{ .reg .u64 t; cvta.to.shared.u64 t, %1; cvt.u32.u64 %0, t; }"
        : "=r"(a) : "l"(p));
    return a;
}
__device__ __forceinline__ uint32_t f2h2(float a, float b) {
    __half2 h = __floats2half2_rn(a, b);
    return *reinterpret_cast<uint32_t*>(&h);
}

#define CP_ASYNC16(dst_u32, src_ptr) \
    asm volatile("cp.async.cg.shared.global [%0], [%1], 16;" \
                 :: "r"(dst_u32), "l"(src_ptr) : "memory")
#define CP_COMMIT() asm volatile("cp.async.commit_group;" ::: "memory")
#define CP_WAIT(n)  asm volatile("cp.async.wait_group %0;" :: "n"(n) : "memory")

__device__ __forceinline__ void mma_f16(float* d, const uint32_t* a, const uint32_t* b) {
    asm volatile(
        "mma.sync.aligned.m16n8k16.row.col.f32.f16.f16.f32 "
        "{%0,%1,%2,%3}, {%4,%5,%6,%7}, {%8,%9}, {%0,%1,%2,%3};"
        : "+f"(d[0]), "+f"(d[1]), "+f"(d[2]), "+f"(d[3])
        : "r"(a[0]), "r"(a[1]), "r"(a[2]), "r"(a[3]), "r"(b[0]), "r"(b[1]));
}

#define LDSM_X4(r0, r1, r2, r3, addr) \
    asm volatile("ldmatrix.sync.aligned.m8n8.x4.shared.b16 {%0,%1,%2,%3}, [%4];" \
                 : "=r"(r0), "=r"(r1), "=r"(r2), "=r"(r3) : "r"(addr))

// ---------------------------------------------------------------------------
// K0: WvT[n][k] = half(Wv[k][n])
// ---------------------------------------------------------------------------
__global__ void wvt_kernel(const float* __restrict__ Wv) {
    __shared__ float t[32][33];
    const int bx = blockIdx.x * 32, by = blockIdx.y * 32;
    const int tx = threadIdx.x, ty = threadIdx.y;
#pragma unroll
    for (int i = 0; i < 32; i += 8)
        t[ty + i][tx] = Wv[(size_t)(by + ty + i) * DD + bx + tx];
    __syncthreads();
#pragma unroll
    for (int i = 0; i < 32; i += 8)
        g_wvTh[(size_t)(bx + ty + i) * DD + by + tx] = __float2half(t[tx][ty + i]);
}

// ---------------------------------------------------------------------------
// K1: smem-GEMM qk + fused xT (half) emission  (unchanged from R14)
// ---------------------------------------------------------------------------
#define QKR 128
#define QKC 64
#define QKPAD 68

__global__ void __launch_bounds__(256, 2)
qk_kernel(const float* __restrict__ x,
          const unsigned char* __restrict__ maskb,
          const float* __restrict__ Wq, const float* __restrict__ bq,
          const float* __restrict__ Wk, const float* __restrict__ bk) {
    __shared__ float xs[QKR * QKPAD];
    __shared__ float ws[QKC * 32];
    const uint32_t xs_u32 = smem_u32(xs);
    const uint32_t ws_u32 = smem_u32(ws);

    const int tid = threadIdx.x;
    const int r0  = blockIdx.x * QKR;
    const int b   = r0 / TT;
    const int sl0 = r0 % TT;

    const int tr = tid >> 3, tc = tid & 7;

    float acc[4][4];
#pragma unroll
    for (int j = 0; j < 4; j++) {
        const int c = tc * 4 + j;
        const float bias = (c < 16) ? bq[c] : bk[c - 16];
#pragma unroll
        for (int i = 0; i < 4; i++) acc[i][j] = bias;
    }

    const int ed   = tid >> 2;
    const int eseg = (tid & 3) * 32;

    for (int ch = 0; ch < 16; ch++) {
        const int k0 = ch * QKC;
        {
            const int kk = tid >> 2, c4 = tid & 3;
            CP_ASYNC16(ws_u32 + (kk * 32 + c4 * 4) * 4,
                       Wq + (size_t)(k0 + kk) * DKK + c4 * 4);
            CP_ASYNC16(ws_u32 + (kk * 32 + 16 + c4 * 4) * 4,
                       Wk + (size_t)(k0 + kk) * DKK + c4 * 4);
        }
#pragma unroll
        for (int it = 0; it < 8; it++) {
            const int idx = tid + it * 256;
            const int row = idx >> 4, c4 = idx & 15;
            CP_ASYNC16(xs_u32 + (row * QKPAD + c4 * 4) * 4,
                       x + (size_t)(r0 + row) * DD + k0 + c4 * 4);
        }
        CP_COMMIT();
        CP_WAIT(0);
        __syncthreads();

#pragma unroll 4
        for (int kk = 0; kk < QKC; kk++) {
            float a[4];
#pragma unroll
            for (int i = 0; i < 4; i++) a[i] = xs[(tr * 4 + i) * QKPAD + kk];
            const float4 w = *reinterpret_cast<const float4*>(&ws[kk * 32 + tc * 4]);
#pragma unroll
            for (int i = 0; i < 4; i++) {
                acc[i][0] += a[i] * w.x;
                acc[i][1] += a[i] * w.y;
                acc[i][2] += a[i] * w.z;
                acc[i][3] += a[i] * w.w;
            }
        }

        {
            __half* dst = g_xTh + (size_t)b * DD * TT + (size_t)(k0 + ed) * TT + sl0 + eseg;
#pragma unroll
            for (int j = 0; j < 4; j++) {
                uint4 v;
                v.x = f2h2(xs[(eseg + 8 * j + 0) * QKPAD + ed], xs[(eseg + 8 * j + 1) * QKPAD + ed]);
                v.y = f2h2(xs[(eseg + 8 * j + 2) * QKPAD + ed], xs[(eseg + 8 * j + 3) * QKPAD + ed]);
                v.z = f2h2(xs[(eseg + 8 * j + 4) * QKPAD + ed], xs[(eseg + 8 * j + 5) * QKPAD + ed]);
                v.w = f2h2(xs[(eseg + 8 * j + 6) * QKPAD + ed], xs[(eseg + 8 * j + 7) * QKPAD + ed]);
                *reinterpret_cast<uint4*>(dst + 8 * j) = v;
            }
        }
        __syncthreads();
    }

    int nz = 0;
#pragma unroll
    for (int p = 0; p < 64; p++)
        if (p & 3) nz |= maskb[p];
    const bool isBool = (nz != 0);

#pragma unroll
    for (int i = 0; i < 4; i++) {
        const int row = r0 + tr * 4 + i;
        const int mv = isBool ? (int)maskb[row]
                              : reinterpret_cast<const int*>(maskb)[row];
#pragma unroll
        for (int j = 0; j < 4; j++) {
            const int c = tc * 4 + j;
            if (c < 16) g_q[row * DKK + c] = acc[i][j];
            else        g_k[row * DKK + (c - 16)] = mv ? NEG_INF : acc[i][j];
        }
    }
}

// ---------------------------------------------------------------------------
// K2: FUSED scores+softmax (row-streamed, fp32) -> P half; Y = P@x fp16 mma
// smem: Psh half 64x520 (66560 B) | region{ ks 512x17 f32 + qs (38912 B),
//        overlaid after scores by 2-stage B ring (2x10240 B) } = 105472 B
// 2 CTAs/SM.
// ---------------------------------------------------------------------------
#define PSTH 520
#define PSH_BYTES (64 * PSTH * 2)            // 66560
#define BKP2H 40
#define BBUF_B (128 * BKP2H * 2)             // 10240
#define KSQS_BYTES (512 * 17 * 4 + 64 * 16 * 4)  // 38912
#define ATT_SMEM_BYTES (PSH_BYTES + KSQS_BYTES)  // 105472

__global__ void __launch_bounds__(256, 2)
attn_kernel() {
    extern __shared__ char smc[];
    __shared__ int s_flag;
    __half* Psh = reinterpret_cast<__half*>(smc);
    char*  region = smc + PSH_BYTES;
    float* ks = reinterpret_cast<float*>(region);
    float* qs = ks + 512 * 17;
    const uint32_t psh_u32 = smem_u32(smc);
    const uint32_t bring_u32 = psh_u32 + PSH_BYTES;

    const int b    = blockIdx.y;
    const int tile = blockIdx.x;
    const int tid  = threadIdx.x;
    const int qbase = b * TT + tile * 64;

    if (tid == 0) s_flag = 0;
    for (int i = tid; i < TT * DKK; i += 256) {
        int s = i >> 4, d = i & 15;
        ks[s * 17 + d] = g_k[(b * TT + s) * DKK + d];
    }
    for (int i = tid; i < 64 * DKK; i += 256)
        qs[i] = g_q[qbase * DKK + i];
    __syncthreads();

    // ---- fused scores + softmax, row-streamed; write P half directly ----
    {
        const int w = tid >> 5, l = tid & 31;
        for (int rr = 0; rr < 8; rr++) {
            const int r  = w * 8 + rr;
            const int tq = tile * 64 + r;
            float qreg[16];
#pragma unroll
            for (int d = 0; d < 16; d++) qreg[d] = qs[r * 16 + d];
            float v[16];
#pragma unroll
            for (int i = 0; i < 16; i++) {
                const int s = l + 32 * i;
                if (s <= tq) {
                    float dot = 0.f;
#pragma unroll
                    for (int d = 0; d < 16; d++) dot += qreg[d] * ks[s * 17 + d];
                    v[i] = dot * 4.0f;
                } else {
                    v[i] = NEG_INF;
                }
            }
            float m = -3.4e38f;
#pragma unroll
            for (int i = 0; i < 16; i++) m = fmaxf(m, v[i]);
#pragma unroll
            for (int off = 16; off > 0; off >>= 1)
                m = fmaxf(m, __shfl_xor_sync(0xffffffffu, m, off));
            if (l == 0 && m < -1e20f) s_flag = 1;
            float ssum = 0.f;
#pragma unroll
            for (int i = 0; i < 16; i++) { v[i] = __expf(v[i] - m); ssum += v[i]; }
#pragma unroll
            for (int off = 16; off > 0; off >>= 1)
                ssum += __shfl_xor_sync(0xffffffffu, ssum, off);
            const float inv = 1.0f / ssum;
#pragma unroll
            for (int i = 0; i < 16; i++)
                Psh[r * PSTH + l + 32 * i] = __float2half(v[i] * inv);
        }
    }
    __syncthreads();   // scores done; ks/qs now dead -> B ring may overwrite

    // ---- Y = P @ x via fp16 mma + ldmatrix, 2-stage ring, causal skip ----
    const int wid = tid >> 5, lane = tid & 31;
    const int wm = (wid >> 2) * 32;
    const int wn = (wid & 3) * 32;
    const int lm = lane >> 2, lk = lane & 3;
    const int lr  = lane & 7;
    const int ah  = (lane >> 3) & 1;
    const int ac  = lane >> 4;

    const uint32_t aAddr0 = psh_u32 + ((wm + ah * 8 + lr) * PSTH + ac * 8) * 2;
    const uint32_t bAddrX4 = bring_u32 +
        ((wn + ((lane >> 4) & 1) * 8 + lr) * BKP2H + ((lane >> 3) & 1) * 8) * 2;

    const __half* xTb = g_xTh + (size_t)b * DD * TT;

    const int nch = s_flag ? 16 : 2 * (tile + 1);   // 32-half k-chunks per nb
    const int tot = 8 * nch;

#define PREF2(NB, KC, BUF) do {                                                      \
        _Pragma("unroll")                                                            \
        for (int t = 0; t < 2; t++) {                                                \
            const int idx = tid + t * 256;                                           \
            const int row = idx >> 2, c8 = idx & 3;                                  \
            CP_ASYNC16(bring_u32 + (BUF) * BBUF_B + (row * BKP2H + c8 * 8) * 2,      \
                       xTb + (size_t)((NB) * 128 + row) * TT + (KC) * 32 + c8 * 8);  \
        }                                                                            \
    } while (0)

    float acc[2][4][4];
#pragma unroll
    for (int i = 0; i < 2; i++)
#pragma unroll
        for (int j = 0; j < 4; j++)
#pragma unroll
            for (int r = 0; r < 4; r++) acc[i][j][r] = 0.f;

    int nbP = 0, kcP = 0;
    PREF2(nbP, kcP, 0); CP_COMMIT();
    if (++kcP == nch) { kcP = 0; nbP++; }

    int nbC = 0, kcC = 0;
    for (int st = 0; st < tot; st++) {
        const int buf = st & 1;
        if (st + 1 < tot) {
            PREF2(nbP, kcP, buf ^ 1); CP_COMMIT();
            if (++kcP == nch) { kcP = 0; nbP++; }
            CP_WAIT(1);
        } else {
            CP_WAIT(0);
        }
        __syncthreads();

        const uint32_t bBuf = bAddrX4 + buf * BBUF_B;
        const int kbase = kcC * 32;
#pragma unroll
        for (int ksu = 0; ksu < 2; ksu++) {
            const int kp = kbase + ksu * 16;
            uint32_t a[2][4], bfr[4][2];
#pragma unroll
            for (int mt = 0; mt < 2; mt++)
                LDSM_X4(a[mt][0], a[mt][1], a[mt][2], a[mt][3],
                        aAddr0 + (mt * 16 * PSTH + kp) * 2);
#pragma unroll
            for (int p = 0; p < 2; p++)
                LDSM_X4(bfr[2 * p][0], bfr[2 * p][1], bfr[2 * p + 1][0], bfr[2 * p + 1][1],
                        bBuf + (p * 16 * BKP2H + ksu * 16) * 2);
#pragma unroll
            for (int mt = 0; mt < 2; mt++)
#pragma unroll
                for (int nt = 0; nt < 4; nt++)
                    mma_f16(acc[mt][nt], a[mt], bfr[nt]);
        }

        if (kcC == nch - 1) {
            const int nb = nbC * 128;
#pragma unroll
            for (int mt = 0; mt < 2; mt++) {
                const int row = qbase + wm + mt * 16 + lm;
#pragma unroll
                for (int nt = 0; nt < 4; nt++) {
                    const int col = nb + wn + nt * 8 + 2 * lk;
                    *reinterpret_cast<uint32_t*>(g_yh + (size_t)row * DD + col) =
                        f2h2(acc[mt][nt][0], acc[mt][nt][1]);
                    *reinterpret_cast<uint32_t*>(g_yh + (size_t)(row + 8) * DD + col) =
                        f2h2(acc[mt][nt][2], acc[mt][nt][3]);
#pragma unroll
                    for (int r = 0; r < 4; r++) acc[mt][nt][r] = 0.f;
                }
            }
        }
        if (++kcC == nch) { kcC = 0; nbC++; }
        __syncthreads();
    }
#undef PREF2
}

// ---------------------------------------------------------------------------
// K3: out = Y @ WvT^T + bv — fp16 mma (unchanged from R14)
// ---------------------------------------------------------------------------
#define BK3H 64
#define BKP3H 72
#define A3_B (128 * BKP3H * 2)          // 18432
#define G3S (2 * A3_B)                  // 36864 per stage (A+B)
#define NST3 (DD / BK3H)                // 16

__global__ void __launch_bounds__(256, 2)
gemm3_mma(const float* __restrict__ bv, float* __restrict__ out) {
    extern __shared__ char smc[];
    const uint32_t sb = smem_u32(smc);

    const int tid  = threadIdx.x;
    const int wid  = tid >> 5, lane = tid & 31;
    const int wm   = (wid >> 2) * 64;
    const int wn   = (wid & 3) * 32;
    const int lm   = lane >> 2, lk = lane & 3;
    const int n0   = blockIdx.x * 128;
    const int m0   = blockIdx.y * 128;

    const __half* Arow = g_yh   + (size_t)m0 * DD;
    const __half* Brow = g_wvTh + (size_t)n0 * DD;

    const int lr = lane & 7;
    const int ah = (lane >> 3) & 1;
    const int ac = lane >> 4;
    const uint32_t aAddr0 = sb + ((wm + ah * 8 + lr) * BKP3H + ac * 8) * 2;
    const uint32_t bAddrX4 = sb + A3_B +
        ((wn + ((lane >> 4) & 1) * 8 + lr) * BKP3H + ((lane >> 3) & 1) * 8) * 2;

#define PREFETCH(S, ST) do {                                                          \
        const int k0 = (S) * BK3H;                                                    \
        _Pragma("unroll")                                                             \
        for (int t = 0; t < 4; t++) {                                                 \
            const int idx = tid + t * 256;                                            \
            const int row = idx >> 3, c8 = idx & 7;                                   \
            CP_ASYNC16(sb + (ST) * G3S + (row * BKP3H + c8 * 8) * 2,                  \
                       Arow + (size_t)row * DD + k0 + c8 * 8);                        \
            CP_ASYNC16(sb + (ST) * G3S + A3_B + (row * BKP3H + c8 * 8) * 2,           \
                       Brow + (size_t)row * DD + k0 + c8 * 8);                        \
        }                                                                             \
    } while (0)

    float acc[4][4][4];
#pragma unroll
    for (int i = 0; i < 4; i++)
#pragma unroll
        for (int j = 0; j < 4; j++)
#pragma unroll
            for (int r = 0; r < 4; r++) acc[i][j][r] = 0.f;

    PREFETCH(0, 0); CP_COMMIT();

    for (int s = 0; s < NST3; s++) {
        const int st = s & 1;
        if (s + 1 < NST3) {
            PREFETCH(s + 1, st ^ 1); CP_COMMIT();
            CP_WAIT(1);
        } else {
            CP_WAIT(0);
        }
        __syncthreads();

        const uint32_t aBuf = aAddr0 + st * G3S;
        const uint32_t bBuf = bAddrX4 + st * G3S;
#pragma unroll
        for (int ksu = 0; ksu < 4; ksu++) {
            uint32_t a[4][4], b[4][2];
#pragma unroll
            for (int mt = 0; mt < 4; mt++)
                LDSM_X4(a[mt][0], a[mt][1], a[mt][2], a[mt][3],
                        aBuf + (mt * 16 * BKP3H + ksu * 16) * 2);
#pragma unroll
            for (int p = 0; p < 2; p++)
                LDSM_X4(b[2 * p][0], b[2 * p][1], b[2 * p + 1][0], b[2 * p + 1][1],
                        bBuf + (p * 16 * BKP3H + ksu * 16) * 2);
#pragma unroll
            for (int mt = 0; mt < 4; mt++)
#pragma unroll
                for (int nt = 0; nt < 4; nt++)
                    mma_f16(acc[mt][nt], a[mt], b[nt]);
        }
        __syncthreads();
    }
#undef PREFETCH

#pragma unroll
    for (int mt = 0; mt < 4; mt++) {
        const int row = m0 + wm + mt * 16 + lm;
#pragma unroll
        for (int nt = 0; nt < 4; nt++) {
            const int col = n0 + wn + nt * 8 + 2 * lk;
            const float b0 = bv[col], b1 = bv[col + 1];
            float2 v0 = { acc[mt][nt][0] + b0, acc[mt][nt][1] + b1 };
            float2 v1 = { acc[mt][nt][2] + b0, acc[mt][nt][3] + b1 };
            *reinterpret_cast<float2*>(out + (size_t)row * DD + col) = v0;
            *reinterpret_cast<float2*>(out + (size_t)(row + 8) * DD + col) = v1;
        }
    }
}

// ---------------------------------------------------------------------------
extern "C" void kernel_launch(void* const* d_in, const int* in_sizes, int n_in,
                              void* d_out, int out_size) {
    const float*         x    = (const float*)d_in[0];
    const unsigned char* mask = (const unsigned char*)d_in[1];
    const float*         Wq   = (const float*)d_in[2];
    const float*         bq   = (const float*)d_in[3];
    const float*         Wk   = (const float*)d_in[4];
    const float*         bk   = (const float*)d_in[5];
    const float*         Wv   = (const float*)d_in[6];
    const float*         bv   = (const float*)d_in[7];
    float* out = (float*)d_out;

    wvt_kernel<<<dim3(32, 32), dim3(32, 8)>>>(Wv);
    qk_kernel<<<BB * TT / QKR, 256>>>(x, mask, Wq, bq, Wk, bk);

    cudaFuncSetAttribute(attn_kernel, cudaFuncAttributeMaxDynamicSharedMemorySize,
                         ATT_SMEM_BYTES);
    attn_kernel<<<dim3(TT / 64, BB), 256, ATT_SMEM_BYTES>>>();

    const size_t gsmem = 2 * G3S;   // 73728 B
    cudaFuncSetAttribute(gemm3_mma, cudaFuncAttributeMaxDynamicSharedMemorySize, (int)gsmem);
    gemm3_mma<<<dim3(DD / 128, BB * TT / 128), 256, gsmem>>>(bv, out);
}

// round 16
// speedup vs baseline: 2.9433x; 1.0380x over previous
#include <cuda_runtime.h>
#include <cuda_fp16.h>
#include <cstdint>

#define BB 64
#define TT 512
#define DD 1024
#define DKK 16
#define NEG_INF (-1e24f)

// scratch (device globals: allocation-free rule)
__device__ float  g_q[BB * TT * DKK];
__device__ float  g_k[BB * TT * DKK];
__device__ __half g_yh[(size_t)BB * TT * DD];
__device__ __half g_wvTh[DD * DD];
__device__ __half g_xTh[(size_t)BB * DD * TT];

// ---------------------------------------------------------------------------
// helpers
// ---------------------------------------------------------------------------
__device__ __forceinline__ uint32_t smem_u32(const void* p) {
    uint32_t a;
    asm("{ .reg .u64 t; cvta.to.shared.u64 t, %1; cvt.u32.u64 %0, t; }"
        : "=r"(a) : "l"(p));
    return a;
}
__device__ __forceinline__ uint32_t f2h2(float a, float b) {
    __half2 h = __floats2half2_rn(a, b);
    return *reinterpret_cast<uint32_t*>(&h);
}

#define CP_ASYNC16(dst_u32, src_ptr) \
    asm volatile("cp.async.cg.shared.global [%0], [%1], 16;" \
                 :: "r"(dst_u32), "l"(src_ptr) : "memory")
#define CP_COMMIT() asm volatile("cp.async.commit_group;" ::: "memory")
#define CP_WAIT(n)  asm volatile("cp.async.wait_group %0;" :: "n"(n) : "memory")

__device__ __forceinline__ void mma_f16(float* d, const uint32_t* a, const uint32_t* b) {
    asm volatile(
        "mma.sync.aligned.m16n8k16.row.col.f32.f16.f16.f32 "
        "{%0,%1,%2,%3}, {%4,%5,%6,%7}, {%8,%9}, {%0,%1,%2,%3};"
        : "+f"(d[0]), "+f"(d[1]), "+f"(d[2]), "+f"(d[3])
        : "r"(a[0]), "r"(a[1]), "r"(a[2]), "r"(a[3]), "r"(b[0]), "r"(b[1]));
}

#define LDSM_X4(r0, r1, r2, r3, addr) \
    asm volatile("ldmatrix.sync.aligned.m8n8.x4.shared.b16 {%0,%1,%2,%3}, [%4];" \
                 : "=r"(r0), "=r"(r1), "=r"(r2), "=r"(r3) : "r"(addr))

// ---------------------------------------------------------------------------
// K0: WvT[n][k] = half(Wv[k][n])
// ---------------------------------------------------------------------------
__global__ void wvt_kernel(const float* __restrict__ Wv) {
    __shared__ float t[32][33];
    const int bx = blockIdx.x * 32, by = blockIdx.y * 32;
    const int tx = threadIdx.x, ty = threadIdx.y;
#pragma unroll
    for (int i = 0; i < 32; i += 8)
        t[ty + i][tx] = Wv[(size_t)(by + ty + i) * DD + bx + tx];
    __syncthreads();
#pragma unroll
    for (int i = 0; i < 32; i += 8)
        g_wvTh[(size_t)(bx + ty + i) * DD + by + tx] = __float2half(t[tx][ty + i]);
}

// ---------------------------------------------------------------------------
// K1: smem-GEMM qk + fused xT (half) emission  (unchanged)
// ---------------------------------------------------------------------------
#define QKR 128
#define QKC 64
#define QKPAD 68

__global__ void __launch_bounds__(256, 2)
qk_kernel(const float* __restrict__ x,
          const unsigned char* __restrict__ maskb,
          const float* __restrict__ Wq, const float* __restrict__ bq,
          const float* __restrict__ Wk, const float* __restrict__ bk) {
    __shared__ float xs[QKR * QKPAD];
    __shared__ float ws[QKC * 32];
    const uint32_t xs_u32 = smem_u32(xs);
    const uint32_t ws_u32 = smem_u32(ws);

    const int tid = threadIdx.x;
    const int r0  = blockIdx.x * QKR;
    const int b   = r0 / TT;
    const int sl0 = r0 % TT;

    const int tr = tid >> 3, tc = tid & 7;

    float acc[4][4];
#pragma unroll
    for (int j = 0; j < 4; j++) {
        const int c = tc * 4 + j;
        const float bias = (c < 16) ? bq[c] : bk[c - 16];
#pragma unroll
        for (int i = 0; i < 4; i++) acc[i][j] = bias;
    }

    const int ed   = tid >> 2;
    const int eseg = (tid & 3) * 32;

    for (int ch = 0; ch < 16; ch++) {
        const int k0 = ch * QKC;
        {
            const int kk = tid >> 2, c4 = tid & 3;
            CP_ASYNC16(ws_u32 + (kk * 32 + c4 * 4) * 4,
                       Wq + (size_t)(k0 + kk) * DKK + c4 * 4);
            CP_ASYNC16(ws_u32 + (kk * 32 + 16 + c4 * 4) * 4,
                       Wk + (size_t)(k0 + kk) * DKK + c4 * 4);
        }
#pragma unroll
        for (int it = 0; it < 8; it++) {
            const int idx = tid + it * 256;
            const int row = idx >> 4, c4 = idx & 15;
            CP_ASYNC16(xs_u32 + (row * QKPAD + c4 * 4) * 4,
                       x + (size_t)(r0 + row) * DD + k0 + c4 * 4);
        }
        CP_COMMIT();
        CP_WAIT(0);
        __syncthreads();

#pragma unroll 4
        for (int kk = 0; kk < QKC; kk++) {
            float a[4];
#pragma unroll
            for (int i = 0; i < 4; i++) a[i] = xs[(tr * 4 + i) * QKPAD + kk];
            const float4 w = *reinterpret_cast<const float4*>(&ws[kk * 32 + tc * 4]);
#pragma unroll
            for (int i = 0; i < 4; i++) {
                acc[i][0] += a[i] * w.x;
                acc[i][1] += a[i] * w.y;
                acc[i][2] += a[i] * w.z;
                acc[i][3] += a[i] * w.w;
            }
        }

        {
            __half* dst = g_xTh + (size_t)b * DD * TT + (size_t)(k0 + ed) * TT + sl0 + eseg;
#pragma unroll
            for (int j = 0; j < 4; j++) {
                uint4 v;
                v.x = f2h2(xs[(eseg + 8 * j + 0) * QKPAD + ed], xs[(eseg + 8 * j + 1) * QKPAD + ed]);
                v.y = f2h2(xs[(eseg + 8 * j + 2) * QKPAD + ed], xs[(eseg + 8 * j + 3) * QKPAD + ed]);
                v.z = f2h2(xs[(eseg + 8 * j + 4) * QKPAD + ed], xs[(eseg + 8 * j + 5) * QKPAD + ed]);
                v.w = f2h2(xs[(eseg + 8 * j + 6) * QKPAD + ed], xs[(eseg + 8 * j + 7) * QKPAD + ed]);
                *reinterpret_cast<uint4*>(dst + 8 * j) = v;
            }
        }
        __syncthreads();
    }

    int nz = 0;
#pragma unroll
    for (int p = 0; p < 64; p++)
        if (p & 3) nz |= maskb[p];
    const bool isBool = (nz != 0);

#pragma unroll
    for (int i = 0; i < 4; i++) {
        const int row = r0 + tr * 4 + i;
        const int mv = isBool ? (int)maskb[row]
                              : reinterpret_cast<const int*>(maskb)[row];
#pragma unroll
        for (int j = 0; j < 4; j++) {
            const int c = tc * 4 + j;
            if (c < 16) g_q[row * DKK + c] = acc[i][j];
            else        g_k[row * DKK + (c - 16)] = mv ? NEG_INF : acc[i][j];
        }
    }
}

// ---------------------------------------------------------------------------
// K2: FUSED scores+softmax -> P half; Y = P@x fp16 mma; 64-half k-chunks
// smem: Psh half 64x520 (66560 B) | region{ ks/qs 38912 B, overlaid by
//        2-stage B ring 2x18432 B } -> total 105472 B, 2 CTAs/SM
// ---------------------------------------------------------------------------
#define PSTH 520
#define PSH_BYTES (64 * PSTH * 2)            // 66560
#define BKP2H 72
#define BBUF_B (128 * BKP2H * 2)             // 18432
#define KSQS_BYTES (512 * 17 * 4 + 64 * 16 * 4)  // 38912
#define ATT_SMEM_BYTES (PSH_BYTES + KSQS_BYTES)  // 105472

__global__ void __launch_bounds__(256, 2)
attn_kernel() {
    extern __shared__ char smc[];
    __shared__ int s_flag;
    __half* Psh = reinterpret_cast<__half*>(smc);
    char*  region = smc + PSH_BYTES;
    float* ks = reinterpret_cast<float*>(region);
    float* qs = ks + 512 * 17;
    const uint32_t psh_u32 = smem_u32(smc);
    const uint32_t bring_u32 = psh_u32 + PSH_BYTES;

    const int b    = blockIdx.y;
    const int tile = blockIdx.x;
    const int tid  = threadIdx.x;
    const int qbase = b * TT + tile * 64;

    if (tid == 0) s_flag = 0;
    for (int i = tid; i < TT * DKK; i += 256) {
        int s = i >> 4, d = i & 15;
        ks[s * 17 + d] = g_k[(b * TT + s) * DKK + d];
    }
    for (int i = tid; i < 64 * DKK; i += 256)
        qs[i] = g_q[qbase * DKK + i];
    __syncthreads();

    // ---- fused scores + softmax, row-streamed; write P half directly ----
    {
        const int w = tid >> 5, l = tid & 31;
        for (int rr = 0; rr < 8; rr++) {
            const int r  = w * 8 + rr;
            const int tq = tile * 64 + r;
            float qreg[16];
#pragma unroll
            for (int d = 0; d < 16; d++) qreg[d] = qs[r * 16 + d];
            float v[16];
#pragma unroll
            for (int i = 0; i < 16; i++) {
                const int s = l + 32 * i;
                if (s <= tq) {
                    float dot = 0.f;
#pragma unroll
                    for (int d = 0; d < 16; d++) dot += qreg[d] * ks[s * 17 + d];
                    v[i] = dot * 4.0f;
                } else {
                    v[i] = NEG_INF;
                }
            }
            float m = -3.4e38f;
#pragma unroll
            for (int i = 0; i < 16; i++) m = fmaxf(m, v[i]);
#pragma unroll
            for (int off = 16; off > 0; off >>= 1)
                m = fmaxf(m, __shfl_xor_sync(0xffffffffu, m, off));
            if (l == 0 && m < -1e20f) s_flag = 1;
            float ssum = 0.f;
#pragma unroll
            for (int i = 0; i < 16; i++) { v[i] = __expf(v[i] - m); ssum += v[i]; }
#pragma unroll
            for (int off = 16; off > 0; off >>= 1)
                ssum += __shfl_xor_sync(0xffffffffu, ssum, off);
            const float inv = 1.0f / ssum;
#pragma unroll
            for (int i = 0; i < 16; i++)
                Psh[r * PSTH + l + 32 * i] = __float2half(v[i] * inv);
        }
    }
    __syncthreads();   // scores done; ks/qs now dead -> B ring may overwrite

    // ---- Y = P @ x via fp16 mma + ldmatrix, 2-stage ring, causal skip ----
    const int wid = tid >> 5, lane = tid & 31;
    const int wm = (wid >> 2) * 32;
    const int wn = (wid & 3) * 32;
    const int lm = lane >> 2, lk = lane & 3;
    const int lr  = lane & 7;
    const int ah  = (lane >> 3) & 1;
    const int ac  = lane >> 4;

    const uint32_t aAddr0 = psh_u32 + ((wm + ah * 8 + lr) * PSTH + ac * 8) * 2;
    const uint32_t bAddrX4 = bring_u32 +
        ((wn + ((lane >> 4) & 1) * 8 + lr) * BKP2H + ((lane >> 3) & 1) * 8) * 2;

    const __half* xTb = g_xTh + (size_t)b * DD * TT;

    const int nch = s_flag ? 8 : (tile + 1);   // 64-half k-chunks per nb
    const int tot = 8 * nch;

    // stage: 128 rows x 64 halves = 1024 x 16B chunks; 4 per thread
#define PREF2(NB, KC, BUF) do {                                                      \
        _Pragma("unroll")                                                            \
        for (int t = 0; t < 4; t++) {                                                \
            const int idx = tid + t * 256;                                           \
            const int row = idx >> 3, c8 = idx & 7;                                  \
            CP_ASYNC16(bring_u32 + (BUF) * BBUF_B + (row * BKP2H + c8 * 8) * 2,      \
                       xTb + (size_t)((NB) * 128 + row) * TT + (KC) * 64 + c8 * 8);  \
        }                                                                            \
    } while (0)

    float acc[2][4][4];
#pragma unroll
    for (int i = 0; i < 2; i++)
#pragma unroll
        for (int j = 0; j < 4; j++)
#pragma unroll
            for (int r = 0; r < 4; r++) acc[i][j][r] = 0.f;

    int nbP = 0, kcP = 0;
    PREF2(nbP, kcP, 0); CP_COMMIT();
    if (++kcP == nch) { kcP = 0; nbP++; }

    int nbC = 0, kcC = 0;
    for (int st = 0; st < tot; st++) {
        const int buf = st & 1;
        if (st + 1 < tot) {
            PREF2(nbP, kcP, buf ^ 1); CP_COMMIT();
            if (++kcP == nch) { kcP = 0; nbP++; }
            CP_WAIT(1);
        } else {
            CP_WAIT(0);
        }
        __syncthreads();

        const uint32_t bBuf = bAddrX4 + buf * BBUF_B;
        const int kbase = kcC * 64;
#pragma unroll
        for (int ksu = 0; ksu < 4; ksu++) {
            const int kp = kbase + ksu * 16;
            uint32_t a[2][4], bfr[4][2];
#pragma unroll
            for (int mt = 0; mt < 2; mt++)
                LDSM_X4(a[mt][0], a[mt][1], a[mt][2], a[mt][3],
                        aAddr0 + (mt * 16 * PSTH + kp) * 2);
#pragma unroll
            for (int p = 0; p < 2; p++)
                LDSM_X4(bfr[2 * p][0], bfr[2 * p][1], bfr[2 * p + 1][0], bfr[2 * p + 1][1],
                        bBuf + (p * 16 * BKP2H + ksu * 16) * 2);
#pragma unroll
            for (int mt = 0; mt < 2; mt++)
#pragma unroll
                for (int nt = 0; nt < 4; nt++)
                    mma_f16(acc[mt][nt], a[mt], bfr[nt]);
        }

        if (kcC == nch - 1) {
            const int nb = nbC * 128;
#pragma unroll
            for (int mt = 0; mt < 2; mt++) {
                const int row = qbase + wm + mt * 16 + lm;
#pragma unroll
                for (int nt = 0; nt < 4; nt++) {
                    const int col = nb + wn + nt * 8 + 2 * lk;
                    *reinterpret_cast<uint32_t*>(g_yh + (size_t)row * DD + col) =
                        f2h2(acc[mt][nt][0], acc[mt][nt][1]);
                    *reinterpret_cast<uint32_t*>(g_yh + (size_t)(row + 8) * DD + col) =
                        f2h2(acc[mt][nt][2], acc[mt][nt][3]);
#pragma unroll
                    for (int r = 0; r < 4; r++) acc[mt][nt][r] = 0.f;
                }
            }
        }
        if (++kcC == nch) { kcC = 0; nbC++; }
        __syncthreads();
    }
#undef PREF2
}

// ---------------------------------------------------------------------------
// K3: out = Y @ WvT^T + bv — fp16 mma (unchanged from R14)
// ---------------------------------------------------------------------------
#define BK3H 64
#define BKP3H 72
#define A3_B (128 * BKP3H * 2)          // 18432
#define G3S (2 * A3_B)                  // 36864 per stage (A+B)
#define NST3 (DD / BK3H)                // 16

__global__ void __launch_bounds__(256, 2)
gemm3_mma(const float* __restrict__ bv, float* __restrict__ out) {
    extern __shared__ char smc[];
    const uint32_t sb = smem_u32(smc);

    const int tid  = threadIdx.x;
    const int wid  = tid >> 5, lane = tid & 31;
    const int wm   = (wid >> 2) * 64;
    const int wn   = (wid & 3) * 32;
    const int lm   = lane >> 2, lk = lane & 3;
    const int n0   = blockIdx.x * 128;
    const int m0   = blockIdx.y * 128;

    const __half* Arow = g_yh   + (size_t)m0 * DD;
    const __half* Brow = g_wvTh + (size_t)n0 * DD;

    const int lr = lane & 7;
    const int ah = (lane >> 3) & 1;
    const int ac = lane >> 4;
    const uint32_t aAddr0 = sb + ((wm + ah * 8 + lr) * BKP3H + ac * 8) * 2;
    const uint32_t bAddrX4 = sb + A3_B +
        ((wn + ((lane >> 4) & 1) * 8 + lr) * BKP3H + ((lane >> 3) & 1) * 8) * 2;

#define PREFETCH(S, ST) do {                                                          \
        const int k0 = (S) * BK3H;                                                    \
        _Pragma("unroll")                                                             \
        for (int t = 0; t < 4; t++) {                                                 \
            const int idx = tid + t * 256;                                            \
            const int row = idx >> 3, c8 = idx & 7;                                   \
            CP_ASYNC16(sb + (ST) * G3S + (row * BKP3H + c8 * 8) * 2,                  \
                       Arow + (size_t)row * DD + k0 + c8 * 8);                        \
            CP_ASYNC16(sb + (ST) * G3S + A3_B + (row * BKP3H + c8 * 8) * 2,           \
                       Brow + (size_t)row * DD + k0 + c8 * 8);                        \
        }                                                                             \
    } while (0)

    float acc[4][4][4];
#pragma unroll
    for (int i = 0; i < 4; i++)
#pragma unroll
        for (int j = 0; j < 4; j++)
#pragma unroll
            for (int r = 0; r < 4; r++) acc[i][j][r] = 0.f;

    PREFETCH(0, 0); CP_COMMIT();

    for (int s = 0; s < NST3; s++) {
        const int st = s & 1;
        if (s + 1 < NST3) {
            PREFETCH(s + 1, st ^ 1); CP_COMMIT();
            CP_WAIT(1);
        } else {
            CP_WAIT(0);
        }
        __syncthreads();

        const uint32_t aBuf = aAddr0 + st * G3S;
        const uint32_t bBuf = bAddrX4 + st * G3S;
#pragma unroll
        for (int ksu = 0; ksu < 4; ksu++) {
            uint32_t a[4][4], b[4][2];
#pragma unroll
            for (int mt = 0; mt < 4; mt++)
                LDSM_X4(a[mt][0], a[mt][1], a[mt][2], a[mt][3],
                        aBuf + (mt * 16 * BKP3H + ksu * 16) * 2);
#pragma unroll
            for (int p = 0; p < 2; p++)
                LDSM_X4(b[2 * p][0], b[2 * p][1], b[2 * p + 1][0], b[2 * p + 1][1],
                        bBuf + (p * 16 * BKP3H + ksu * 16) * 2);
#pragma unroll
            for (int mt = 0; mt < 4; mt++)
#pragma unroll
                for (int nt = 0; nt < 4; nt++)
                    mma_f16(acc[mt][nt], a[mt], b[nt]);
        }
        __syncthreads();
    }
#undef PREFETCH

#pragma unroll
    for (int mt = 0; mt < 4; mt++) {
        const int row = m0 + wm + mt * 16 + lm;
#pragma unroll
        for (int nt = 0; nt < 4; nt++) {
            const int col = n0 + wn + nt * 8 + 2 * lk;
            const float b0 = bv[col], b1 = bv[col + 1];
            float2 v0 = { acc[mt][nt][0] + b0, acc[mt][nt][1] + b1 };
            float2 v1 = { acc[mt][nt][2] + b0, acc[mt][nt][3] + b1 };
            *reinterpret_cast<float2*>(out + (size_t)row * DD + col) = v0;
            *reinterpret_cast<float2*>(out + (size_t)(row + 8) * DD + col) = v1;
        }
    }
}

// ---------------------------------------------------------------------------
extern "C" void kernel_launch(void* const* d_in, const int* in_sizes, int n_in,
                              void* d_out, int out_size) {
    const float*         x    = (const float*)d_in[0];
    const unsigned char* mask = (const unsigned char*)d_in[1];
    const float*         Wq   = (const float*)d_in[2];
    const float*         bq   = (const float*)d_in[3];
    const float*         Wk   = (const float*)d_in[4];
    const float*         bk   = (const float*)d_in[5];
    const float*         Wv   = (const float*)d_in[6];
    const float*         bv   = (const float*)d_in[7];
    float* out = (float*)d_out;

    wvt_kernel<<<dim3(32, 32), dim3(32, 8)>>>(Wv);
    qk_kernel<<<BB * TT / QKR, 256>>>(x, mask, Wq, bq, Wk, bk);

    cudaFuncSetAttribute(attn_kernel, cudaFuncAttributeMaxDynamicSharedMemorySize,
                         ATT_SMEM_BYTES);
    attn_kernel<<<dim3(TT / 64, BB), 256, ATT_SMEM_BYTES>>>();

    const size_t gsmem = 2 * G3S;   // 73728 B
    cudaFuncSetAttribute(gemm3_mma, cudaFuncAttributeMaxDynamicSharedMemorySize, (int)gsmem);
    gemm3_mma<<<dim3(DD / 128, BB * TT / 128), 256, gsmem>>>(bv, out);
}

// round 17
// speedup vs baseline: 3.0273x; 1.0285x over previous
#include <cuda_runtime.h>
#include <cuda_fp16.h>
#include <cstdint>

#define BB 64
#define TT 512
#define DD 1024
#define DKK 16
#define NEG_INF (-1e24f)

// scratch (device globals: allocation-free rule)
__device__ float  g_q[BB * TT * DKK];
__device__ float  g_k[BB * TT * DKK];
__device__ __half g_yh[(size_t)BB * TT * DD];
__device__ __half g_wvTh[DD * DD];
__device__ __half g_xh[(size_t)BB * TT * DD];   // row-major half(x)

// ---------------------------------------------------------------------------
// helpers
// ---------------------------------------------------------------------------
__device__ __forceinline__ uint32_t smem_u32(const void* p) {
    uint32_t a;
    asm("{ .reg .u64 t; cvta.to.shared.u64 t, %1; cvt.u32.u64 %0, t; }"
        : "=r"(a) : "l"(p));
    return a;
}
__device__ __forceinline__ uint32_t f2h2(float a, float b) {
    __half2 h = __floats2half2_rn(a, b);
    return *reinterpret_cast<uint32_t*>(&h);
}

#define CP_ASYNC16(dst_u32, src_ptr) \
    asm volatile("cp.async.cg.shared.global [%0], [%1], 16;" \
                 :: "r"(dst_u32), "l"(src_ptr) : "memory")
#define CP_COMMIT() asm volatile("cp.async.commit_group;" ::: "memory")
#define CP_WAIT(n)  asm volatile("cp.async.wait_group %0;" :: "n"(n) : "memory")

__device__ __forceinline__ void mma_f16(float* d, const uint32_t* a, const uint32_t* b) {
    asm volatile(
        "mma.sync.aligned.m16n8k16.row.col.f32.f16.f16.f32 "
        "{%0,%1,%2,%3}, {%4,%5,%6,%7}, {%8,%9}, {%0,%1,%2,%3};"
        : "+f"(d[0]), "+f"(d[1]), "+f"(d[2]), "+f"(d[3])
        : "r"(a[0]), "r"(a[1]), "r"(a[2]), "r"(a[3]), "r"(b[0]), "r"(b[1]));
}

#define LDSM_X4(r0, r1, r2, r3, addr) \
    asm volatile("ldmatrix.sync.aligned.m8n8.x4.shared.b16 {%0,%1,%2,%3}, [%4];" \
                 : "=r"(r0), "=r"(r1), "=r"(r2), "=r"(r3) : "r"(addr))
#define LDSM_X4_T(r0, r1, r2, r3, addr) \
    asm volatile("ldmatrix.sync.aligned.m8n8.x4.trans.shared.b16 {%0,%1,%2,%3}, [%4];" \
                 : "=r"(r0), "=r"(r1), "=r"(r2), "=r"(r3) : "r"(addr))

// ---------------------------------------------------------------------------
// K0: WvT[n][k] = half(Wv[k][n])   (unchanged)
// ---------------------------------------------------------------------------
__global__ void wvt_kernel(const float* __restrict__ Wv) {
    __shared__ float t[32][33];
    const int bx = blockIdx.x * 32, by = blockIdx.y * 32;
    const int tx = threadIdx.x, ty = threadIdx.y;
#pragma unroll
    for (int i = 0; i < 32; i += 8)
        t[ty + i][tx] = Wv[(size_t)(by + ty + i) * DD + bx + tx];
    __syncthreads();
#pragma unroll
    for (int i = 0; i < 32; i += 8)
        g_wvTh[(size_t)(bx + ty + i) * DD + by + tx] = __float2half(t[tx][ty + i]);
}

// ---------------------------------------------------------------------------
// K1: smem-GEMM qk + ROW-MAJOR xh emission (no transpose, no conflicts)
// ---------------------------------------------------------------------------
#define QKR 128
#define QKC 64
#define QKPAD 68

__global__ void __launch_bounds__(256, 2)
qk_kernel(const float* __restrict__ x,
          const unsigned char* __restrict__ maskb,
          const float* __restrict__ Wq, const float* __restrict__ bq,
          const float* __restrict__ Wk, const float* __restrict__ bk) {
    __shared__ float xs[QKR * QKPAD];
    __shared__ float ws[QKC * 32];
    const uint32_t xs_u32 = smem_u32(xs);
    const uint32_t ws_u32 = smem_u32(ws);

    const int tid = threadIdx.x;
    const int r0  = blockIdx.x * QKR;

    const int tr = tid >> 3, tc = tid & 7;

    float acc[4][4];
#pragma unroll
    for (int j = 0; j < 4; j++) {
        const int c = tc * 4 + j;
        const float bias = (c < 16) ? bq[c] : bk[c - 16];
#pragma unroll
        for (int i = 0; i < 4; i++) acc[i][j] = bias;
    }

    for (int ch = 0; ch < 16; ch++) {
        const int k0 = ch * QKC;
        {
            const int kk = tid >> 2, c4 = tid & 3;
            CP_ASYNC16(ws_u32 + (kk * 32 + c4 * 4) * 4,
                       Wq + (size_t)(k0 + kk) * DKK + c4 * 4);
            CP_ASYNC16(ws_u32 + (kk * 32 + 16 + c4 * 4) * 4,
                       Wk + (size_t)(k0 + kk) * DKK + c4 * 4);
        }
#pragma unroll
        for (int it = 0; it < 8; it++) {
            const int idx = tid + it * 256;
            const int row = idx >> 4, c4 = idx & 15;
            CP_ASYNC16(xs_u32 + (row * QKPAD + c4 * 4) * 4,
                       x + (size_t)(r0 + row) * DD + k0 + c4 * 4);
        }
        CP_COMMIT();
        CP_WAIT(0);
        __syncthreads();

#pragma unroll 4
        for (int kk = 0; kk < QKC; kk++) {
            float a[4];
#pragma unroll
            for (int i = 0; i < 4; i++) a[i] = xs[(tr * 4 + i) * QKPAD + kk];
            const float4 w = *reinterpret_cast<const float4*>(&ws[kk * 32 + tc * 4]);
#pragma unroll
            for (int i = 0; i < 4; i++) {
                acc[i][0] += a[i] * w.x;
                acc[i][1] += a[i] * w.y;
                acc[i][2] += a[i] * w.z;
                acc[i][3] += a[i] * w.w;
            }
        }

        // emit xh row-major: rows r0..r0+127, cols k0..k0+63 (coalesced)
        {
            __half* dst = g_xh + (size_t)r0 * DD + k0;
#pragma unroll
            for (int t = 0; t < 4; t++) {
                const int idx = tid + t * 256;       // 0..1023 = 128 rows x 8 segs
                const int row = idx >> 3, seg = idx & 7;
                const float4 a0 = *reinterpret_cast<const float4*>(&xs[row * QKPAD + seg * 8]);
                const float4 a1 = *reinterpret_cast<const float4*>(&xs[row * QKPAD + seg * 8 + 4]);
                uint4 v;
                v.x = f2h2(a0.x, a0.y); v.y = f2h2(a0.z, a0.w);
                v.z = f2h2(a1.x, a1.y); v.w = f2h2(a1.z, a1.w);
                *reinterpret_cast<uint4*>(dst + (size_t)row * DD + seg * 8) = v;
            }
        }
        __syncthreads();
    }

    int nz = 0;
#pragma unroll
    for (int p = 0; p < 64; p++)
        if (p & 3) nz |= maskb[p];
    const bool isBool = (nz != 0);

#pragma unroll
    for (int i = 0; i < 4; i++) {
        const int row = r0 + tr * 4 + i;
        const int mv = isBool ? (int)maskb[row]
                              : reinterpret_cast<const int*>(maskb)[row];
#pragma unroll
        for (int j = 0; j < 4; j++) {
            const int c = tc * 4 + j;
            if (c < 16) g_q[row * DKK + c] = acc[i][j];
            else        g_k[row * DKK + (c - 16)] = mv ? NEG_INF : acc[i][j];
        }
    }
}

// ---------------------------------------------------------------------------
// K2: FUSED scores+softmax -> P half; Y = P@x via fp16 mma + ldmatrix.trans
// B tiles: [64 s][128 d] half, stride 136, staged from row-major g_xh.
// smem: Psh 66560 B | region{ ks/qs 38912 B, overlaid by 2x17408 B ring }
// ---------------------------------------------------------------------------
#define PSTH 520
#define PSH_BYTES (64 * PSTH * 2)            // 66560
#define STRH 136
#define BBUF_B (64 * STRH * 2)               // 17408
#define KSQS_BYTES (512 * 17 * 4 + 64 * 16 * 4)  // 38912
#define ATT_SMEM_BYTES (PSH_BYTES + KSQS_BYTES)  // 105472

__global__ void __launch_bounds__(256, 2)
attn_kernel() {
    extern __shared__ char smc[];
    __shared__ int s_flag;
    __half* Psh = reinterpret_cast<__half*>(smc);
    char*  region = smc + PSH_BYTES;
    float* ks = reinterpret_cast<float*>(region);
    float* qs = ks + 512 * 17;
    const uint32_t psh_u32 = smem_u32(smc);
    const uint32_t bring_u32 = psh_u32 + PSH_BYTES;

    const int b    = blockIdx.y;
    const int tile = blockIdx.x;
    const int tid  = threadIdx.x;
    const int qbase = b * TT + tile * 64;

    if (tid == 0) s_flag = 0;
    for (int i = tid; i < TT * DKK; i += 256) {
        int s = i >> 4, d = i & 15;
        ks[s * 17 + d] = g_k[(b * TT + s) * DKK + d];
    }
    for (int i = tid; i < 64 * DKK; i += 256)
        qs[i] = g_q[qbase * DKK + i];
    __syncthreads();

    // ---- fused scores + softmax, row-streamed; write P half directly ----
    {
        const int w = tid >> 5, l = tid & 31;
        for (int rr = 0; rr < 8; rr++) {
            const int r  = w * 8 + rr;
            const int tq = tile * 64 + r;
            float qreg[16];
#pragma unroll
            for (int d = 0; d < 16; d++) qreg[d] = qs[r * 16 + d];
            float v[16];
#pragma unroll
            for (int i = 0; i < 16; i++) {
                const int s = l + 32 * i;
                if (s <= tq) {
                    float dot = 0.f;
#pragma unroll
                    for (int d = 0; d < 16; d++) dot += qreg[d] * ks[s * 17 + d];
                    v[i] = dot * 4.0f;
                } else {
                    v[i] = NEG_INF;
                }
            }
            float m = -3.4e38f;
#pragma unroll
            for (int i = 0; i < 16; i++) m = fmaxf(m, v[i]);
#pragma unroll
            for (int off = 16; off > 0; off >>= 1)
                m = fmaxf(m, __shfl_xor_sync(0xffffffffu, m, off));
            if (l == 0 && m < -1e20f) s_flag = 1;
            float ssum = 0.f;
#pragma unroll
            for (int i = 0; i < 16; i++) { v[i] = __expf(v[i] - m); ssum += v[i]; }
#pragma unroll
            for (int off = 16; off > 0; off >>= 1)
                ssum += __shfl_xor_sync(0xffffffffu, ssum, off);
            const float inv = 1.0f / ssum;
#pragma unroll
            for (int i = 0; i < 16; i++)
                Psh[r * PSTH + l + 32 * i] = __float2half(v[i] * inv);
        }
    }
    __syncthreads();   // scores done; ks/qs dead -> B ring may overwrite

    // ---- Y = P @ x via fp16 mma, B via ldmatrix.trans from [s][d] tiles ----
    const int wid = tid >> 5, lane = tid & 31;
    const int wm = (wid >> 2) * 32;
    const int wn = (wid & 3) * 32;
    const int lm = lane >> 2, lk = lane & 3;
    const int lr  = lane & 7;
    const int ah  = (lane >> 3) & 1;
    const int ac  = lane >> 4;

    const uint32_t aAddr0 = psh_u32 + ((wm + ah * 8 + lr) * PSTH + ac * 8) * 2;
    // trans B: lane -> row (k within 16) = ((lane>>3)&1)*8 + lr ; col = wn + (lane>>4)*8
    const uint32_t bAddrT = bring_u32 +
        (((((lane >> 3) & 1) * 8 + lr) * STRH) + wn + (lane >> 4) * 8) * 2;

    const __half* xhb = g_xh + (size_t)b * TT * DD;

    const int nch = s_flag ? 8 : (tile + 1);   // 64-s chunks per nb
    const int tot = 8 * nch;

    // stage: 64 s-rows x 128 d halves = 1024 x 16B chunks; 4 per thread
#define PREF2(NB, KC, BUF) do {                                                      \
        _Pragma("unroll")                                                            \
        for (int t = 0; t < 4; t++) {                                                \
            const int idx = tid + t * 256;                                           \
            const int row = idx >> 4, c8 = idx & 15;                                 \
            CP_ASYNC16(bring_u32 + (BUF) * BBUF_B + (row * STRH + c8 * 8) * 2,       \
                       xhb + (size_t)((KC) * 64 + row) * DD + (NB) * 128 + c8 * 8);  \
        }                                                                            \
    } while (0)

    float acc[2][4][4];
#pragma unroll
    for (int i = 0; i < 2; i++)
#pragma unroll
        for (int j = 0; j < 4; j++)
#pragma unroll
            for (int r = 0; r < 4; r++) acc[i][j][r] = 0.f;

    int nbP = 0, kcP = 0;
    PREF2(nbP, kcP, 0); CP_COMMIT();
    if (++kcP == nch) { kcP = 0; nbP++; }

    int nbC = 0, kcC = 0;
    for (int st = 0; st < tot; st++) {
        const int buf = st & 1;
        if (st + 1 < tot) {
            PREF2(nbP, kcP, buf ^ 1); CP_COMMIT();
            if (++kcP == nch) { kcP = 0; nbP++; }
            CP_WAIT(1);
        } else {
            CP_WAIT(0);
        }
        __syncthreads();

        const uint32_t bBuf = bAddrT + buf * BBUF_B;
        const int kbase = kcC * 64;
#pragma unroll
        for (int ksu = 0; ksu < 4; ksu++) {
            const int kp = kbase + ksu * 16;
            uint32_t a[2][4], bfr[4][2];
#pragma unroll
            for (int mt = 0; mt < 2; mt++)
                LDSM_X4(a[mt][0], a[mt][1], a[mt][2], a[mt][3],
                        aAddr0 + (mt * 16 * PSTH + kp) * 2);
#pragma unroll
            for (int p = 0; p < 2; p++)
                LDSM_X4_T(bfr[2 * p][0], bfr[2 * p][1], bfr[2 * p + 1][0], bfr[2 * p + 1][1],
                          bBuf + (ksu * 16 * STRH + p * 16) * 2);
#pragma unroll
            for (int mt = 0; mt < 2; mt++)
#pragma unroll
                for (int nt = 0; nt < 4; nt++)
                    mma_f16(acc[mt][nt], a[mt], bfr[nt]);
        }

        if (kcC == nch - 1) {
            const int nb = nbC * 128;
#pragma unroll
            for (int mt = 0; mt < 2; mt++) {
                const int row = qbase + wm + mt * 16 + lm;
#pragma unroll
                for (int nt = 0; nt < 4; nt++) {
                    const int col = nb + wn + nt * 8 + 2 * lk;
                    *reinterpret_cast<uint32_t*>(g_yh + (size_t)row * DD + col) =
                        f2h2(acc[mt][nt][0], acc[mt][nt][1]);
                    *reinterpret_cast<uint32_t*>(g_yh + (size_t)(row + 8) * DD + col) =
                        f2h2(acc[mt][nt][2], acc[mt][nt][3]);
#pragma unroll
                    for (int r = 0; r < 4; r++) acc[mt][nt][r] = 0.f;
                }
            }
        }
        if (++kcC == nch) { kcC = 0; nbC++; }
        __syncthreads();
    }
#undef PREF2
}

// ---------------------------------------------------------------------------
// K3: out = Y @ WvT^T + bv — fp16 mma (unchanged)
// ---------------------------------------------------------------------------
#define BK3H 64
#define BKP3H 72
#define A3_B (128 * BKP3H * 2)          // 18432
#define G3S (2 * A3_B)                  // 36864 per stage (A+B)
#define NST3 (DD / BK3H)                // 16

__global__ void __launch_bounds__(256, 2)
gemm3_mma(const float* __restrict__ bv, float* __restrict__ out) {
    extern __shared__ char smc[];
    const uint32_t sb = smem_u32(smc);

    const int tid  = threadIdx.x;
    const int wid  = tid >> 5, lane = tid & 31;
    const int wm   = (wid >> 2) * 64;
    const int wn   = (wid & 3) * 32;
    const int lm   = lane >> 2, lk = lane & 3;
    const int n0   = blockIdx.x * 128;
    const int m0   = blockIdx.y * 128;

    const __half* Arow = g_yh   + (size_t)m0 * DD;
    const __half* Brow = g_wvTh + (size_t)n0 * DD;

    const int lr = lane & 7;
    const int ah = (lane >> 3) & 1;
    const int ac = lane >> 4;
    const uint32_t aAddr0 = sb + ((wm + ah * 8 + lr) * BKP3H + ac * 8) * 2;
    const uint32_t bAddrX4 = sb + A3_B +
        ((wn + ((lane >> 4) & 1) * 8 + lr) * BKP3H + ((lane >> 3) & 1) * 8) * 2;

#define PREFETCH(S, ST) do {                                                          \
        const int k0 = (S) * BK3H;                                                    \
        _Pragma("unroll")                                                             \
        for (int t = 0; t < 4; t++) {                                                 \
            const int idx = tid + t * 256;                                            \
            const int row = idx >> 3, c8 = idx & 7;                                   \
            CP_ASYNC16(sb + (ST) * G3S + (row * BKP3H + c8 * 8) * 2,                  \
                       Arow + (size_t)row * DD + k0 + c8 * 8);                        \
            CP_ASYNC16(sb + (ST) * G3S + A3_B + (row * BKP3H + c8 * 8) * 2,           \
                       Brow + (size_t)row * DD + k0 + c8 * 8);                        \
        }                                                                             \
    } while (0)

    float acc[4][4][4];
#pragma unroll
    for (int i = 0; i < 4; i++)
#pragma unroll
        for (int j = 0; j < 4; j++)
#pragma unroll
            for (int r = 0; r < 4; r++) acc[i][j][r] = 0.f;

    PREFETCH(0, 0); CP_COMMIT();

    for (int s = 0; s < NST3; s++) {
        const int st = s & 1;
        if (s + 1 < NST3) {
            PREFETCH(s + 1, st ^ 1); CP_COMMIT();
            CP_WAIT(1);
        } else {
            CP_WAIT(0);
        }
        __syncthreads();

        const uint32_t aBuf = aAddr0 + st * G3S;
        const uint32_t bBuf = bAddrX4 + st * G3S;
#pragma unroll
        for (int ksu = 0; ksu < 4; ksu++) {
            uint32_t a[4][4], b[4][2];
#pragma unroll
            for (int mt = 0; mt < 4; mt++)
                LDSM_X4(a[mt][0], a[mt][1], a[mt][2], a[mt][3],
                        aBuf + (mt * 16 * BKP3H + ksu * 16) * 2);
#pragma unroll
            for (int p = 0; p < 2; p++)
                LDSM_X4(b[2 * p][0], b[2 * p][1], b[2 * p + 1][0], b[2 * p + 1][1],
                        bBuf + (p * 16 * BKP3H + ksu * 16) * 2);
#pragma unroll
            for (int mt = 0; mt < 4; mt++)
#pragma unroll
                for (int nt = 0; nt < 4; nt++)
                    mma_f16(acc[mt][nt], a[mt], b[nt]);
        }
        __syncthreads();
    }
#undef PREFETCH

#pragma unroll
    for (int mt = 0; mt < 4; mt++) {
        const int row = m0 + wm + mt * 16 + lm;
#pragma unroll
        for (int nt = 0; nt < 4; nt++) {
            const int col = n0 + wn + nt * 8 + 2 * lk;
            const float b0 = bv[col], b1 = bv[col + 1];
            float2 v0 = { acc[mt][nt][0] + b0, acc[mt][nt][1] + b1 };
            float2 v1 = { acc[mt][nt][2] + b0, acc[mt][nt][3] + b1 };
            *reinterpret_cast<float2*>(out + (size_t)row * DD + col) = v0;
            *reinterpret_cast<float2*>(out + (size_t)(row + 8) * DD + col) = v1;
        }
    }
}

// ---------------------------------------------------------------------------
extern "C" void kernel_launch(void* const* d_in, const int* in_sizes, int n_in,
                              void* d_out, int out_size) {
    const float*         x    = (const float*)d_in[0];
    const unsigned char* mask = (const unsigned char*)d_in[1];
    const float*         Wq   = (const float*)d_in[2];
    const float*         bq   = (const float*)d_in[3];
    const float*         Wk   = (const float*)d_in[4];
    const float*         bk   = (const float*)d_in[5];
    const float*         Wv   = (const float*)d_in[6];
    const float*         bv   = (const float*)d_in[7];
    float* out = (float*)d_out;

    wvt_kernel<<<dim3(32, 32), dim3(32, 8)>>>(Wv);
    qk_kernel<<<BB * TT / QKR, 256>>>(x, mask, Wq, bq, Wk, bk);

    cudaFuncSetAttribute(attn_kernel, cudaFuncAttributeMaxDynamicSharedMemorySize,
                         ATT_SMEM_BYTES);
    attn_kernel<<<dim3(TT / 64, BB), 256, ATT_SMEM_BYTES>>>();

    const size_t gsmem = 2 * G3S;   // 73728 B
    cudaFuncSetAttribute(gemm3_mma, cudaFuncAttributeMaxDynamicSharedMemorySize, (int)gsmem);
    gemm3_mma<<<dim3(DD / 128, BB * TT / 128), 256, gsmem>>>(bv, out);
}